// round 13
// baseline (speedup 1.0000x reference)
#include <cuda_runtime.h>
#include <cuda_fp16.h>
#include <math.h>
#include <stdint.h>

// ---------------- problem constants ----------------
#define BB   4
#define NSP  1500
#define MPAD 1536          // padded rows per batch (12 tiles of 128)
#define NN   6000
#define N4   (NN*4)
#define EE   120000
#define HH   384
#define HWPX (HH*HH)       // 147456
#define HS   96
#define HWI  (HS*HS)       // 9216
#define CC   256
#define NPOOL 512
#define CSR_E (EE+NN)
#define SIGMA_INV 5.0f

// GEMM tiling
#define BM 128
#define BN 64
#define BK 32
#define KPAD (BK+8)        // 40 halves = 80B row stride: 16B-aligned, conflict-free
#define KSTEPS (HWI/BK)    // 288

// ---------------- scratch ----------------
__device__ __half g_Wh[(size_t)BB*MPAD*HWI];   // 113 MB dense pooling matrix (fp16)
__device__ __half g_Bh[(size_t)BB*NPOOL*HWI];  // 37.7 MB feats fp16, [b][n][q] K-major
__device__ float g_pool[(size_t)NN*NPOOL];
__device__ float g_Za[NN*CC];
__device__ float g_xw[NN*CC];
__device__ float g_cnt[NN];
__device__ float g_sumI4[N4*3];
__device__ float g_deg[NN];
__device__ float g_dis[NN];
__device__ float g_wnn[EE];
__device__ int   g_picnt[N4];
__device__ int   g_ecnt[NN];
__device__ int   g_eoff[NN+1];
__device__ int   g_efill[NN];
__device__ int   g_csr_src[CSR_E];
__device__ float g_csr_nrm[CSR_E];
__device__ float g_wn[15*CC];

// ---------------- helpers ----------------
__device__ __forceinline__ uint32_t smem_u32(const void* p) {
    uint32_t a;
    asm("{ .reg .u64 t; cvta.to.shared.u64 t, %1; cvt.u32.u64 %0, t; }" : "=r"(a) : "l"(p));
    return a;
}
#define CP_ASYNC16(dst, src) \
    asm volatile("cp.async.cg.shared.global [%0], [%1], 16;" :: "r"(dst), "l"(src))

// ---------------- 1: zero W ----------------
__global__ void k_zeroW() {
    size_t n4 = (size_t)BB*MPAD*HWI/8;
    uint4 z = make_uint4(0,0,0,0);
    for (size_t i = (size_t)blockIdx.x*blockDim.x + threadIdx.x; i < n4;
         i += (size_t)gridDim.x*blockDim.x)
        reinterpret_cast<uint4*>(g_Wh)[i] = z;
}

// ---------------- 2: build dense W (4 half atomics per pixel, low contention) ---
__global__ void k_buildW(const int* __restrict__ labels) {
    int yx = blockIdx.x*blockDim.x + threadIdx.x;
    int y = yx / HH, x = yx % HH;
    const float scale = 95.0f/383.0f;
    float fy = y*scale, fx = x*scale;
    int y0 = (int)floorf(fy); if (y0 > 95) y0 = 95;
    int x0 = (int)floorf(fx); if (x0 > 95) x0 = 95;
    float wy = fy - y0, wx = fx - x0;
    int y1 = min(y0+1, 95), x1 = min(x0+1, 95);
    __half h00 = __float2half((1.f-wy)*(1.f-wx));
    __half h01 = __float2half((1.f-wy)*wx);
    __half h10 = __float2half(wy*(1.f-wx));
    __half h11 = __float2half(wy*wx);
    int q00 = y0*HS+x0, q01 = y0*HS+x1, q10 = y1*HS+x0, q11 = y1*HS+x1;
    #pragma unroll
    for (int b = 0; b < BB; b++) {
        int s = labels[b*HWPX + yx];
        __half* Wr = g_Wh + ((size_t)b*MPAD + s)*HWI;
        atomicAdd(Wr + q00, h00);
        atomicAdd(Wr + q01, h01);
        atomicAdd(Wr + q10, h10);
        atomicAdd(Wr + q11, h11);
    }
}

// ---------------- 3: convert feats fp32 -> fp16 [b][n][q] K-major ---------------
__global__ void k_convert(const float* __restrict__ f0, const float* __restrict__ f1) {
    size_t t = (size_t)blockIdx.x*blockDim.x + threadIdx.x;
    size_t total = (size_t)BB*NPOOL*HWI/4;
    if (t >= total) return;
    size_t flat = t*4;
    int b = (int)(flat / ((size_t)NPOOL*HWI));
    size_t r = flat % ((size_t)NPOOL*HWI);
    int n = (int)(r / HWI), q = (int)(r % HWI);
    const float* src = ((n >> 8) ? f1 : f0) + ((size_t)(b*CC + (n & 255)))*HWI + q;
    float4 v = *reinterpret_cast<const float4*>(src);
    __half2 h0 = __floats2half2_rn(v.x, v.y);
    __half2 h1 = __floats2half2_rn(v.z, v.w);
    uint2 o;
    o.x = *reinterpret_cast<unsigned*>(&h0);
    o.y = *reinterpret_cast<unsigned*>(&h1);
    *reinterpret_cast<uint2*>(&g_Bh[flat]) = o;
}

// ---------------- 4: HMMA pooling GEMM  D = W @ B^T  (K=9216) -------------------
// mma.sync.m16n8k16.row.col; CTA 256 thr = 4(m) x 2(n) warps; warp tile 32x32.
__global__ void __launch_bounds__(256) k_hgemm() {
    __shared__ __align__(16) __half As[2][BM][KPAD];
    __shared__ __align__(16) __half Bs[2][BN][KPAD];
    int tid = threadIdx.x, lane = tid & 31, warp = tid >> 5;
    int wm = warp & 3, wn = warp >> 2;
    int mtile = blockIdx.x, ntile = blockIdx.y, b = blockIdx.z;
    const __half* Wp = g_Wh + ((size_t)b*MPAD + mtile*BM)*HWI;
    const __half* Bp = g_Bh + ((size_t)b*NPOOL + ntile*BN)*HWI;
    int gq = lane >> 2, tq = lane & 3;          // groupID, threadID_in_group

    auto load_stage = [&](int ks, int st) {
        int k0 = ks*BK;
        #pragma unroll
        for (int it = 0; it < 2; it++) {        // A: 512 x 16B
            int idx = it*256 + tid;
            int r = idx >> 2, c = idx & 3;
            CP_ASYNC16(smem_u32(&As[st][r][c*8]), Wp + (size_t)r*HWI + k0 + c*8);
        }
        {                                       // B: 256 x 16B
            int r = tid >> 2, c = tid & 3;
            CP_ASYNC16(smem_u32(&Bs[st][r][c*8]), Bp + (size_t)r*HWI + k0 + c*8);
        }
        asm volatile("cp.async.commit_group;" ::: "memory");
    };

    float acc[2][4][4];
    #pragma unroll
    for (int i = 0; i < 2; i++)
        #pragma unroll
        for (int j = 0; j < 4; j++)
            #pragma unroll
            for (int k = 0; k < 4; k++) acc[i][j][k] = 0.f;

    load_stage(0, 0);
    load_stage(1, 1);

    for (int ks = 0; ks < KSTEPS; ks++) {
        int st = ks & 1;
        if (ks + 1 < KSTEPS) asm volatile("cp.async.wait_group 1;" ::: "memory");
        else                 asm volatile("cp.async.wait_group 0;" ::: "memory");
        __syncthreads();

        #pragma unroll
        for (int kk = 0; kk < BK; kk += 16) {
            uint32_t a[2][4], bf[4][2];
            #pragma unroll
            for (int fm = 0; fm < 2; fm++) {
                int r = wm*32 + fm*16 + gq;
                a[fm][0] = *(const uint32_t*)&As[st][r    ][kk + tq*2];
                a[fm][1] = *(const uint32_t*)&As[st][r + 8][kk + tq*2];
                a[fm][2] = *(const uint32_t*)&As[st][r    ][kk + 8 + tq*2];
                a[fm][3] = *(const uint32_t*)&As[st][r + 8][kk + 8 + tq*2];
            }
            #pragma unroll
            for (int fn = 0; fn < 4; fn++) {
                int c = wn*32 + fn*8 + gq;
                bf[fn][0] = *(const uint32_t*)&Bs[st][c][kk + tq*2];
                bf[fn][1] = *(const uint32_t*)&Bs[st][c][kk + 8 + tq*2];
            }
            #pragma unroll
            for (int fm = 0; fm < 2; fm++)
                #pragma unroll
                for (int fn = 0; fn < 4; fn++)
                    asm volatile(
                        "mma.sync.aligned.m16n8k16.row.col.f32.f16.f16.f32 "
                        "{%0,%1,%2,%3}, {%4,%5,%6,%7}, {%8,%9}, {%0,%1,%2,%3};"
                        : "+f"(acc[fm][fn][0]), "+f"(acc[fm][fn][1]),
                          "+f"(acc[fm][fn][2]), "+f"(acc[fm][fn][3])
                        : "r"(a[fm][0]), "r"(a[fm][1]), "r"(a[fm][2]), "r"(a[fm][3]),
                          "r"(bf[fn][0]), "r"(bf[fn][1]));
        }
        __syncthreads();
        if (ks + 2 < KSTEPS) load_stage(ks + 2, st);
    }

    // epilogue: write D rows (< NSP) to g_pool
    #pragma unroll
    for (int fm = 0; fm < 2; fm++) {
        #pragma unroll
        for (int fn = 0; fn < 4; fn++) {
            int m = mtile*BM + wm*32 + fm*16 + gq;
            int n = ntile*BN + wn*32 + fn*8 + tq*2;
            if (m < NSP) {
                float2 v = make_float2(acc[fm][fn][0], acc[fm][fn][1]);
                *reinterpret_cast<float2*>(&g_pool[(size_t)(b*NSP + m)*NPOOL + n]) = v;
            }
            if (m + 8 < NSP) {
                float2 v = make_float2(acc[fm][fn][2], acc[fm][fn][3]);
                *reinterpret_cast<float2*>(&g_pool[(size_t)(b*NSP + m + 8)*NPOOL + n]) = v;
            }
        }
    }
}

// ---------------- 5: init (self-healing) ----------------
__global__ void k_init() {
    int i = blockIdx.x*blockDim.x + threadIdx.x;
    if (i >= NN) return;
    g_ecnt[i] = 0; g_efill[i] = 0;
    g_deg[i] = 0.f;
    #pragma unroll
    for (int k = 0; k < 4; k++) {
        g_picnt[i*4+k] = 0;
        g_sumI4[(i*4+k)*3+0] = 0.f;
        g_sumI4[(i*4+k)*3+1] = 0.f;
        g_sumI4[(i*4+k)*3+2] = 0.f;
    }
}

// ---------------- 6: sharded counts + image sums ----------------
__global__ void k_build1(const int* __restrict__ labels, const float* __restrict__ image) {
    int yx = blockIdx.x*blockDim.x + threadIdx.x;
    int shard = yx & 3;
    #pragma unroll
    for (int b = 0; b < BB; b++) {
        int s = b*NSP + labels[b*HWPX + yx];
        int cidx = s*4 + shard;
        atomicAdd(&g_picnt[cidx], 1);
        #pragma unroll
        for (int c = 0; c < 3; c++)
            atomicAdd(&g_sumI4[cidx*3+c], image[(size_t)(b*3+c)*HWPX + yx]);
    }
}

// ---------------- 7: edge weights + degree ----------------
__global__ void k_edge_w_deg(const int* __restrict__ edges, const float* __restrict__ probas) {
    int e = blockIdx.x*blockDim.x + threadIdx.x;
    if (e >= EE) return;
    int src = edges[e], dst = edges[EE + e];
    float w = expf(-fabsf(probas[src] - probas[dst]) * SIGMA_INV);
    g_wnn[e] = w;
    atomicAdd(&g_deg[dst], w);
    atomicAdd(&g_ecnt[dst], 1);
}

// ---------------- 8: scan edge counts + dis + cnt ----------------
__global__ void k_scanE() {
    __shared__ int wsum[32];
    int t = threadIdx.x, lane = t & 31, w = t >> 5;
    int loc[6]; int s = 0;
    #pragma unroll
    for (int i = 0; i < 6; i++) {
        int idx = t*6 + i;
        int v = (idx < NN) ? (g_ecnt[idx] + 1) : 0;
        loc[i] = s; s += v;
        if (idx < NN) {
            float d = g_deg[idx] + 2.0f;
            g_dis[idx] = rsqrtf(fmaxf(d, 1e-30f));
            g_cnt[idx] = (float)(g_picnt[4*idx] + g_picnt[4*idx+1]
                               + g_picnt[4*idx+2] + g_picnt[4*idx+3]);
        }
    }
    int x = s;
    #pragma unroll
    for (int o = 1; o < 32; o <<= 1) {
        int y = __shfl_up_sync(0xffffffffu, x, o);
        if (lane >= o) x += y;
    }
    if (lane == 31) wsum[w] = x;
    __syncthreads();
    if (w == 0) {
        int y = wsum[lane];
        #pragma unroll
        for (int o = 1; o < 32; o <<= 1) {
            int z2 = __shfl_up_sync(0xffffffffu, y, o);
            if (lane >= o) y += z2;
        }
        wsum[lane] = y;
    }
    __syncthreads();
    int base = (w > 0 ? wsum[w-1] : 0) + x - s;
    #pragma unroll
    for (int i = 0; i < 6; i++) {
        int idx = t*6 + i;
        if (idx < NN) g_eoff[idx] = base + loc[i];
    }
    if (t == 1023) g_eoff[NN] = base + s;
}

// ---------------- 9: edge CSR scatter ----------------
__global__ void k_edge_scatter(const int* __restrict__ edges) {
    int i = blockIdx.x*blockDim.x + threadIdx.x;
    if (i >= EE + NN) return;
    if (i < EE) {
        int src = edges[i], dst = edges[EE + i];
        float w = g_wnn[i];
        int j = g_eoff[dst] + atomicAdd(&g_efill[dst], 1);
        g_csr_src[j] = src;
        g_csr_nrm[j] = g_dis[src] * w * g_dis[dst];
    } else {
        int n = i - EE;
        int j = g_eoff[n+1] - 1;
        g_csr_src[j] = n;
        g_csr_nrm[j] = 2.0f * g_dis[n] * g_dis[n];
    }
}

// ---------------- GCN ----------------
__global__ void k_x0(const float* __restrict__ W0) {
    __shared__ float z0[3];
    int n = blockIdx.x, c = threadIdx.x;
    if (c < 3) {
        float v = g_sumI4[(n*4+0)*3+c] + g_sumI4[(n*4+1)*3+c]
                + g_sumI4[(n*4+2)*3+c] + g_sumI4[(n*4+3)*3+c];
        z0[c] = v / fmaxf(g_cnt[n], 1.0f);
    }
    __syncthreads();
    g_xw[(size_t)n*CC + c] = z0[0]*W0[c] + z0[1]*W0[CC+c] + z0[2]*W0[2*CC+c];
}

__global__ void k_agg_relu(const float* __restrict__ xw, const float* __restrict__ bias,
                           float* __restrict__ out) {
    int tid = threadIdx.x;
    int team = tid >> 6, lane = tid & 63;
    int n = blockIdx.x*4 + team;
    const float4* __restrict__ xw4 = reinterpret_cast<const float4*>(xw);
    float4 bv = reinterpret_cast<const float4*>(bias)[lane];
    int s = g_eoff[n], e = g_eoff[n+1];
    float4 a0 = make_float4(0.f,0.f,0.f,0.f);
    float4 a1 = make_float4(0.f,0.f,0.f,0.f);
    int j = s;
    for (; j + 1 < e; j += 2) {
        int   sc0 = __ldg(&g_csr_src[j]);
        int   sc1 = __ldg(&g_csr_src[j+1]);
        float nr0 = __ldg(&g_csr_nrm[j]);
        float nr1 = __ldg(&g_csr_nrm[j+1]);
        float4 v0 = xw4[(size_t)sc0*64 + lane];
        float4 v1 = xw4[(size_t)sc1*64 + lane];
        a0.x = fmaf(nr0, v0.x, a0.x); a0.y = fmaf(nr0, v0.y, a0.y);
        a0.z = fmaf(nr0, v0.z, a0.z); a0.w = fmaf(nr0, v0.w, a0.w);
        a1.x = fmaf(nr1, v1.x, a1.x); a1.y = fmaf(nr1, v1.y, a1.y);
        a1.z = fmaf(nr1, v1.z, a1.z); a1.w = fmaf(nr1, v1.w, a1.w);
    }
    if (j < e) {
        int   sc0 = __ldg(&g_csr_src[j]);
        float nr0 = __ldg(&g_csr_nrm[j]);
        float4 v0 = xw4[(size_t)sc0*64 + lane];
        a0.x = fmaf(nr0, v0.x, a0.x); a0.y = fmaf(nr0, v0.y, a0.y);
        a0.z = fmaf(nr0, v0.z, a0.z); a0.w = fmaf(nr0, v0.w, a0.w);
    }
    float4 r;
    r.x = fmaxf(a0.x + a1.x + bv.x, 0.f); r.y = fmaxf(a0.y + a1.y + bv.y, 0.f);
    r.z = fmaxf(a0.z + a1.z + bv.z, 0.f); r.w = fmaxf(a0.w + a1.w + bv.w, 0.f);
    reinterpret_cast<float4*>(out)[(size_t)n*64 + lane] = r;
}

// ---------------- SGEMM with fused mix A-operand ----------------
__global__ void k_sgemm_mix(const float* __restrict__ Za, const float* __restrict__ B,
                            float* __restrict__ C, int offF) {
    __shared__ float As[8][128];
    __shared__ float Bs[8][64];
    int tid = threadIdx.x;
    int tx = tid & 15, ty = tid >> 4;
    int m0 = blockIdx.y*128, n0 = blockIdx.x*64;
    float acc[8][4];
    #pragma unroll
    for (int i=0;i<8;i++)
        #pragma unroll
        for (int j=0;j<4;j++) acc[i][j]=0.f;

    int a_m = tid >> 1;
    int a_k = (tid & 1) * 4;
    int b_k = tid >> 5;
    int b_n = (tid & 31) * 2;
    int m = m0 + a_m;
    bool mok = (m < NN);
    float inv = mok ? 0.5f / fmaxf(g_cnt[m], 1.0f) : 0.f;
    const float* poolRow = g_pool + (size_t)(mok ? m : 0)*NPOOL + offF;
    const float* zaRow   = Za     + (size_t)(mok ? m : 0)*CC;

    for (int kt = 0; kt < CC; kt += 8) {
        float4 av = make_float4(0.f,0.f,0.f,0.f);
        if (mok) {
            float4 hp = *reinterpret_cast<const float4*>(poolRow + kt + a_k);
            float4 za = *reinterpret_cast<const float4*>(zaRow   + kt + a_k);
            av.x = hp.x*inv + 0.5f*za.x; av.y = hp.y*inv + 0.5f*za.y;
            av.z = hp.z*inv + 0.5f*za.z; av.w = hp.w*inv + 0.5f*za.w;
        }
        As[a_k+0][a_m]=av.x; As[a_k+1][a_m]=av.y;
        As[a_k+2][a_m]=av.z; As[a_k+3][a_m]=av.w;
        float2 bv = *reinterpret_cast<const float2*>(B + (size_t)(kt+b_k)*CC + n0 + b_n);
        Bs[b_k][b_n]=bv.x; Bs[b_k][b_n+1]=bv.y;
        __syncthreads();
        #pragma unroll
        for (int k = 0; k < 8; k++) {
            float ar[8], br[4];
            #pragma unroll
            for (int i=0;i<8;i++) ar[i]=As[k][ty*8+i];
            #pragma unroll
            for (int j=0;j<4;j++) br[j]=Bs[k][tx*4+j];
            #pragma unroll
            for (int i=0;i<8;i++)
                #pragma unroll
                for (int j=0;j<4;j++) acc[i][j] = fmaf(ar[i], br[j], acc[i][j]);
        }
        __syncthreads();
    }
    #pragma unroll
    for (int i = 0; i < 8; i++) {
        int mm = m0 + ty*8 + i;
        if (mm < NN) {
            #pragma unroll
            for (int j = 0; j < 4; j++)
                C[(size_t)mm*CC + n0 + tx*4 + j] = acc[i][j];
        }
    }
}

// ---------------- epilogue ----------------
__global__ void k_norm_lin(const float* __restrict__ lin_w) {
    __shared__ float red[8];
    int c = threadIdx.x, lane = c & 31, w = c >> 5;
    for (int k = 0; k < 15; k++) {
        float v = lin_w[k*CC + c];
        float sq = v*v;
        #pragma unroll
        for (int o = 16; o > 0; o >>= 1) sq += __shfl_xor_sync(0xffffffffu, sq, o);
        if (lane == 0) red[w] = sq;
        __syncthreads();
        float tot = 0.f;
        #pragma unroll
        for (int i = 0; i < 8; i++) tot += red[i];
        g_wn[k*CC + c] = v / sqrtf(tot);
        __syncthreads();
    }
}

__global__ void k_out(const float* __restrict__ Z, float* __restrict__ outp) {
    __shared__ float sh[CC];
    __shared__ float red[8];
    int n = blockIdx.x, c = threadIdx.x;
    int lane = c & 31, w = c >> 5;
    float z = Z[(size_t)n*CC + c];
    float sq = z*z;
    #pragma unroll
    for (int o = 16; o > 0; o >>= 1) sq += __shfl_xor_sync(0xffffffffu, sq, o);
    if (lane == 0) red[w] = sq;
    __syncthreads();
    float tot = 0.f;
    #pragma unroll
    for (int i = 0; i < 8; i++) tot += red[i];
    float nrm = fmaxf(sqrtf(tot), 1e-12f);
    float v = z / nrm;
    outp[(size_t)NN*15 + (size_t)n*CC + c] = v;   // cs_r
    sh[c] = v;
    __syncthreads();
    for (int k = w; k < 15; k += 8) {
        float d = 0.f;
        for (int i = lane; i < CC; i += 32) d = fmaf(sh[i], g_wn[k*CC + i], d);
        #pragma unroll
        for (int o = 16; o > 0; o >>= 1) d += __shfl_xor_sync(0xffffffffu, d, o);
        if (lane == 0) outp[(size_t)n*15 + k] = d;   // cs
    }
}

// ---------------- launch ----------------
extern "C" void kernel_launch(void* const* d_in, const int* in_sizes, int n_in,
                              void* d_out, int out_size) {
    const float* image  = (const float*)d_in[0];
    const int*   labels = (const int*)  d_in[1];
    const int*   edges  = (const int*)  d_in[2];
    const float* probas = (const float*)d_in[3];
    const float* feats0 = (const float*)d_in[4];
    const float* feats1 = (const float*)d_in[5];
    const float* W0     = (const float*)d_in[6];
    const float* b0     = (const float*)d_in[7];
    const float* W1     = (const float*)d_in[8];
    const float* b1     = (const float*)d_in[9];
    const float* W2     = (const float*)d_in[10];
    const float* b2     = (const float*)d_in[11];
    const float* lin_w  = (const float*)d_in[12];
    float* outp = (float*)d_out;

    float *pZa, *pXw;
    cudaGetSymbolAddress((void**)&pZa, g_Za);
    cudaGetSymbolAddress((void**)&pXw, g_xw);

    // 1-4: dense pooling path (launch #4 = k_hgemm, lands in ncu window)
    k_zeroW<<<4096, 256>>>();
    k_buildW<<<HWPX/256, 256>>>(labels);
    k_convert<<<(int)(((size_t)BB*NPOOL*HWI/4 + 255)/256), 256>>>(feats0, feats1);
    k_hgemm<<<dim3(MPAD/BM, NPOOL/BN, BB), 256>>>();
    // 5-6: node stats
    k_init<<<(NN+255)/256, 256>>>();
    k_build1<<<HWPX/256, 256>>>(labels, image);
    // 7-9: graph build
    k_edge_w_deg<<<(EE+255)/256, 256>>>(edges, probas);
    k_scanE<<<1, 1024>>>();
    k_edge_scatter<<<(EE+NN+255)/256, 256>>>(edges);
    // 10: epilogue prep
    k_norm_lin<<<1, CC>>>(lin_w);
    // 11-12: layer 1 (image)
    k_x0<<<NN, CC>>>(W0);
    k_agg_relu<<<NN/4, 256>>>(pXw, b0, pZa);
    // 13-14: layer 2 (feats0)
    k_sgemm_mix<<<dim3(CC/64, (NN+127)/128), 256>>>(pZa, W1, pXw, 0);
    k_agg_relu<<<NN/4, 256>>>(pXw, b1, pZa);
    // 15-16: layer 3 (feats1)
    k_sgemm_mix<<<dim3(CC/64, (NN+127)/128), 256>>>(pZa, W2, pXw, CC);
    k_agg_relu<<<NN/4, 256>>>(pXw, b2, pZa);
    // 17: output
    k_out<<<NN, CC>>>(pZa, outp);
    (void)in_sizes; (void)n_in; (void)out_size;
}

// round 14
// speedup vs baseline: 1.5342x; 1.5342x over previous
#include <cuda_runtime.h>
#include <cuda_fp16.h>
#include <math.h>
#include <stdint.h>

// ---------------- problem constants ----------------
#define BB   4
#define NSP  1500
#define NN   6000          // BB*NSP
#define N4   (NN*4)        // sharded counters (4 shards per superpixel)
#define EE   120000
#define HH   384
#define HWPX (HH*HH)       // 147456
#define NPX  (BB*HWPX)     // 589824
#define HS   96
#define HWI  (HS*HS)       // 9216
#define CC   256
#define NPOOL 512          // feats0 | feats1 columns
#define NENT (2*NPX)       // 1179648 pair-compressed pooling entries
#define CSR_E (EE+NN)      // folded self loops: one entry each, weight 2*dis^2
#define SIGMA_INV 5.0f     // 1/0.2

// ---------------- scratch (device globals; k_init re-inits every call) ----------
__device__ __half g_Bmh[(size_t)BB*HWI*NPOOL + NPOOL]; // 37.7 MB + 1 pad row
__device__ int4  g_ent4[NENT/2];                 // (q,w2,q,w2) pairs, 9.4 MB
__device__ float g_pool[(size_t)NN*NPOOL];
__device__ float g_Za[NN*CC];
__device__ float g_xw[NN*CC];
__device__ float g_cnt[NN];
__device__ float g_sumI4[N4*3];  // sharded image sums
__device__ float g_deg[NN];      // self-loop +2 folded into dis computation
__device__ float g_dis[NN];
__device__ float g_wnn[EE];
__device__ int   g_picnt[N4];    // sharded pooling counts
__device__ int   g_pfill4[N4];   // sharded fill cursors
__device__ int   g_poff4[N4+1];  // sharded offsets; s's range = [4s, 4s+4)
__device__ int   g_ecnt[NN];     // +1 self slot folded into scanE
__device__ int   g_eoff[NN+1];
__device__ int   g_efill[NN];
__device__ int   g_csr_src[CSR_E];
__device__ float g_csr_nrm[CSR_E];
__device__ float g_wn[15*CC];

// ---------------- 0: init (self-healing regardless of prior stream state) -------
__global__ void k_init() {
    int i = blockIdx.x*blockDim.x + threadIdx.x;
    if (i >= NN) return;
    g_ecnt[i] = 0; g_efill[i] = 0;
    g_deg[i] = 0.f;
    #pragma unroll
    for (int k = 0; k < 4; k++) {
        g_picnt[i*4+k] = 0; g_pfill4[i*4+k] = 0;
        g_sumI4[(i*4+k)*3+0] = 0.f;
        g_sumI4[(i*4+k)*3+1] = 0.f;
        g_sumI4[(i*4+k)*3+2] = 0.f;
    }
}

// ---------------- 1: sharded counts + image sums (4 batches per thread) ---------
__global__ void k_build1(const int* __restrict__ labels, const float* __restrict__ image) {
    int yx = blockIdx.x*blockDim.x + threadIdx.x;   // 0..HWPX-1
    int shard = yx & 3;
    #pragma unroll
    for (int b = 0; b < BB; b++) {
        int s = b*NSP + labels[b*HWPX + yx];
        int cidx = s*4 + shard;
        atomicAdd(&g_picnt[cidx], 1);
        #pragma unroll
        for (int c = 0; c < 3; c++)
            atomicAdd(&g_sumI4[cidx*3+c], image[(size_t)(b*3+c)*HWPX + yx]);
    }
}

// ---------------- 2: scan 24000 sharded pooling counts (x2, warp-shuffle) -------
__global__ void k_scanP() {   // 1024 threads, 24 elems each
    __shared__ int wsum[32];
    int t = threadIdx.x, lane = t & 31, w = t >> 5;
    int loc[24]; int s = 0;
    #pragma unroll
    for (int i = 0; i < 24; i++) {
        int idx = t*24 + i;
        int v = (idx < N4) ? 2*g_picnt[idx] : 0;
        loc[i] = s; s += v;
    }
    int x = s;
    #pragma unroll
    for (int o = 1; o < 32; o <<= 1) {
        int y = __shfl_up_sync(0xffffffffu, x, o);
        if (lane >= o) x += y;
    }
    if (lane == 31) wsum[w] = x;
    __syncthreads();
    if (w == 0) {
        int y = wsum[lane];
        #pragma unroll
        for (int o = 1; o < 32; o <<= 1) {
            int z2 = __shfl_up_sync(0xffffffffu, y, o);
            if (lane >= o) y += z2;
        }
        wsum[lane] = y;
    }
    __syncthreads();
    int base = (w > 0 ? wsum[w-1] : 0) + x - s;   // exclusive prefix of this thread
    #pragma unroll
    for (int i = 0; i < 24; i++) {
        int idx = t*24 + i;
        if (idx < N4) g_poff4[idx] = base + loc[i];
    }
    if (t == 1023) g_poff4[N4] = base + s;
}

// ---------------- 3: pooling entries (sharded cursors, bilinear once) -----------
__global__ void k_build2(const int* __restrict__ labels) {
    int yx = blockIdx.x*blockDim.x + threadIdx.x;   // 0..HWPX-1
    int shard = yx & 3;
    int y = yx / HH, x = yx % HH;

    const float scale = 95.0f/383.0f;
    float fy = y*scale, fx = x*scale;
    int y0 = (int)floorf(fy); if (y0 > 95) y0 = 95;
    int x0 = (int)floorf(fx); if (x0 > 95) x0 = 95;
    float wy = fy - y0, wx = fx - x0;
    int y1 = min(y0+1, 95);

    float w00 = (1.f-wy)*(1.f-wx), w01 = (1.f-wy)*wx;
    float w10 = wy*(1.f-wx),       w11 = wy*wx;
    if (x0 == 95) { w00 += w01; w01 = 0.f; w10 += w11; w11 = 0.f; }
    __half2 wt = __floats2half2_rn(w00, w01);
    __half2 wb = __floats2half2_rn(w10, w11);
    int wti = *reinterpret_cast<int*>(&wt);
    int wbi = *reinterpret_cast<int*>(&wb);
    int qt = y0*HS + x0, qb = y1*HS + x0;

    #pragma unroll
    for (int b = 0; b < BB; b++) {
        int s = b*NSP + labels[b*HWPX + yx];
        int cidx = s*4 + shard;
        int pos = g_poff4[cidx] + atomicAdd(&g_pfill4[cidx], 2);   // pos % 2 == 0
        int4 e;
        e.x = b*HWI + qt;  e.y = wti;
        e.z = b*HWI + qb;  e.w = wbi;
        g_ent4[pos>>1] = e;
    }
}

// ---------------- 4: feats transpose NCHW -> fp16 (b*9216, 512) ------------------
__global__ void k_transpose(const float* __restrict__ f0, const float* __restrict__ f1) {
    __shared__ float t[32][33];
    int z = blockIdx.z;                 // 0..7
    int b = z & 3;
    int colOff = (z >> 2) * CC;
    const float* __restrict__ src = (z < 4) ? f0 : f1;
    int q0 = blockIdx.x*32, c0 = blockIdx.y*32;
    int tx = threadIdx.x, ty = threadIdx.y;     // 32 x 8
    #pragma unroll
    for (int i = 0; i < 32; i += 8) {
        int c = c0 + ty + i, q = q0 + tx;
        t[ty+i][tx] = src[((size_t)b*CC + c)*HWI + q];
    }
    __syncthreads();
    int tid = ty*32 + tx;
    int qrow = tid >> 3, cg = tid & 7;
    __half2 h0 = __floats2half2_rn(t[cg*4+0][qrow], t[cg*4+1][qrow]);
    __half2 h1 = __floats2half2_rn(t[cg*4+2][qrow], t[cg*4+3][qrow]);
    uint2 o;
    o.x = *reinterpret_cast<unsigned*>(&h0);
    o.y = *reinterpret_cast<unsigned*>(&h1);
    size_t base = ((size_t)b*HWI + q0 + qrow)*NPOOL + colOff + c0 + cg*4;
    *reinterpret_cast<uint2*>(&g_Bmh[base]) = o;
}

// ---------------- 5: sparse pooling SpMM (pair entries) ----------------
// 256 thr = 4 teams x 64 lanes; per entry: two adjacent rows, one half2 weight.
__device__ __forceinline__ void acc8(float* acc, float w, uint4 v) {
    float2 f0 = __half22float2(*(const __half2*)&v.x);
    float2 f1 = __half22float2(*(const __half2*)&v.y);
    float2 f2 = __half22float2(*(const __half2*)&v.z);
    float2 f3 = __half22float2(*(const __half2*)&v.w);
    acc[0] = fmaf(w, f0.x, acc[0]); acc[1] = fmaf(w, f0.y, acc[1]);
    acc[2] = fmaf(w, f1.x, acc[2]); acc[3] = fmaf(w, f1.y, acc[3]);
    acc[4] = fmaf(w, f2.x, acc[4]); acc[5] = fmaf(w, f2.y, acc[5]);
    acc[6] = fmaf(w, f3.x, acc[6]); acc[7] = fmaf(w, f3.y, acc[7]);
}

__global__ void k_spmm() {
    __shared__ int2  sh[256];
    __shared__ float red[4][512];
    int s = blockIdx.x;
    int tid = threadIdx.x;
    int team = tid >> 6, lane = tid & 63;
    int beg = g_poff4[4*s], end = g_poff4[4*s+4];
    const uint4* __restrict__ B4 = reinterpret_cast<const uint4*>(g_Bmh);
    const int2* __restrict__ ent = reinterpret_cast<const int2*>(g_ent4);
    float acc[8];
    #pragma unroll
    for (int i = 0; i < 8; i++) acc[i] = 0.f;

    for (int c0 = beg; c0 < end; c0 += 256) {
        int m = min(256, end - c0);
        __syncthreads();
        if (tid < m) sh[tid] = ent[c0 + tid];
        __syncthreads();
        for (int j = team; j < m; j += 4) {
            int2 e = sh[j];
            float2 wv = __half22float2(*reinterpret_cast<__half2*>(&e.y));
            size_t r = (size_t)e.x*64 + lane;
            uint4 vlo = B4[r];
            uint4 vhi = B4[r + 64];
            acc8(acc, wv.x, vlo);
            acc8(acc, wv.y, vhi);
        }
    }
    #pragma unroll
    for (int i = 0; i < 8; i++) red[team][lane*8+i] = acc[i];
    __syncthreads();
    #pragma unroll
    for (int c = tid; c < 512; c += 256)
        g_pool[(size_t)s*NPOOL + c] = red[0][c] + red[1][c] + red[2][c] + red[3][c];
}

// ---------------- 6: edge weights + degree + per-dst counts ----------------
__global__ void k_edge_w_deg(const int* __restrict__ edges, const float* __restrict__ probas) {
    int e = blockIdx.x*blockDim.x + threadIdx.x;
    if (e >= EE) return;
    int src = edges[e], dst = edges[EE + e];
    float w = expf(-fabsf(probas[src] - probas[dst]) * SIGMA_INV);
    g_wnn[e] = w;
    atomicAdd(&g_deg[dst], w);
    atomicAdd(&g_ecnt[dst], 1);
}

// ---------------- 7: scan edge counts (+1 self slot) + dis + cnt ----------------
__global__ void k_scanE() {
    __shared__ int wsum[32];
    int t = threadIdx.x, lane = t & 31, w = t >> 5;
    int loc[6]; int s = 0;
    #pragma unroll
    for (int i = 0; i < 6; i++) {
        int idx = t*6 + i;
        int v = (idx < NN) ? (g_ecnt[idx] + 1) : 0;
        loc[i] = s; s += v;
        if (idx < NN) {
            float d = g_deg[idx] + 2.0f;
            g_dis[idx] = rsqrtf(fmaxf(d, 1e-30f));
            g_cnt[idx] = 0.5f * (float)(g_poff4[4*idx+4] - g_poff4[4*idx]);
        }
    }
    int x = s;
    #pragma unroll
    for (int o = 1; o < 32; o <<= 1) {
        int y = __shfl_up_sync(0xffffffffu, x, o);
        if (lane >= o) x += y;
    }
    if (lane == 31) wsum[w] = x;
    __syncthreads();
    if (w == 0) {
        int y = wsum[lane];
        #pragma unroll
        for (int o = 1; o < 32; o <<= 1) {
            int z2 = __shfl_up_sync(0xffffffffu, y, o);
            if (lane >= o) y += z2;
        }
        wsum[lane] = y;
    }
    __syncthreads();
    int base = (w > 0 ? wsum[w-1] : 0) + x - s;
    #pragma unroll
    for (int i = 0; i < 6; i++) {
        int idx = t*6 + i;
        if (idx < NN) g_eoff[idx] = base + loc[i];
    }
    if (t == 1023) g_eoff[NN] = base + s;
}

// ---------------- 8: edge CSR scatter (self loop -> last slot, no atomic) ------
__global__ void k_edge_scatter(const int* __restrict__ edges) {
    int i = blockIdx.x*blockDim.x + threadIdx.x;
    if (i >= EE + NN) return;
    if (i < EE) {
        int src = edges[i], dst = edges[EE + i];
        float w = g_wnn[i];
        int j = g_eoff[dst] + atomicAdd(&g_efill[dst], 1);
        g_csr_src[j] = src;
        g_csr_nrm[j] = g_dis[src] * w * g_dis[dst];
    } else {
        int n = i - EE;
        int j = g_eoff[n+1] - 1;
        g_csr_src[j] = n;
        g_csr_nrm[j] = 2.0f * g_dis[n] * g_dis[n];
    }
}

// ---------------- GCN ----------------
__global__ void k_x0(const float* __restrict__ W0) {   // xw = (sumI/cnt) @ W0 (K=3)
    __shared__ float z0[3];
    int n = blockIdx.x, c = threadIdx.x;
    if (c < 3) {
        float v = g_sumI4[(n*4+0)*3+c] + g_sumI4[(n*4+1)*3+c]
                + g_sumI4[(n*4+2)*3+c] + g_sumI4[(n*4+3)*3+c];
        z0[c] = v / fmaxf(g_cnt[n], 1.0f);
    }
    __syncthreads();
    g_xw[(size_t)n*CC + c] = z0[0]*W0[c] + z0[1]*W0[CC+c] + z0[2]*W0[2*CC+c];
}

// 256 thr = 4 teams x 64 lanes; lane owns 4 cols via float4. grid = NN/4.
__global__ void k_agg_relu(const float* __restrict__ xw, const float* __restrict__ bias,
                           float* __restrict__ out) {
    int tid = threadIdx.x;
    int team = tid >> 6, lane = tid & 63;
    int n = blockIdx.x*4 + team;
    const float4* __restrict__ xw4 = reinterpret_cast<const float4*>(xw);
    float4 bv = reinterpret_cast<const float4*>(bias)[lane];
    int s = g_eoff[n], e = g_eoff[n+1];
    float4 a0 = make_float4(0.f,0.f,0.f,0.f);
    float4 a1 = make_float4(0.f,0.f,0.f,0.f);
    int j = s;
    for (; j + 1 < e; j += 2) {
        int   sc0 = __ldg(&g_csr_src[j]);
        int   sc1 = __ldg(&g_csr_src[j+1]);
        float nr0 = __ldg(&g_csr_nrm[j]);
        float nr1 = __ldg(&g_csr_nrm[j+1]);
        float4 v0 = xw4[(size_t)sc0*64 + lane];
        float4 v1 = xw4[(size_t)sc1*64 + lane];
        a0.x = fmaf(nr0, v0.x, a0.x); a0.y = fmaf(nr0, v0.y, a0.y);
        a0.z = fmaf(nr0, v0.z, a0.z); a0.w = fmaf(nr0, v0.w, a0.w);
        a1.x = fmaf(nr1, v1.x, a1.x); a1.y = fmaf(nr1, v1.y, a1.y);
        a1.z = fmaf(nr1, v1.z, a1.z); a1.w = fmaf(nr1, v1.w, a1.w);
    }
    if (j < e) {
        int   sc0 = __ldg(&g_csr_src[j]);
        float nr0 = __ldg(&g_csr_nrm[j]);
        float4 v0 = xw4[(size_t)sc0*64 + lane];
        a0.x = fmaf(nr0, v0.x, a0.x); a0.y = fmaf(nr0, v0.y, a0.y);
        a0.z = fmaf(nr0, v0.z, a0.z); a0.w = fmaf(nr0, v0.w, a0.w);
    }
    float4 r;
    r.x = fmaxf(a0.x + a1.x + bv.x, 0.f); r.y = fmaxf(a0.y + a1.y + bv.y, 0.f);
    r.z = fmaxf(a0.z + a1.z + bv.z, 0.f); r.w = fmaxf(a0.w + a1.w + bv.w, 0.f);
    reinterpret_cast<float4*>(out)[(size_t)n*64 + lane] = r;
}

// ---------------- SGEMM with fused mix A-operand ----------------
// C = A' @ B, A'[m][k] = 0.5*pool[m][offF+k]/cnt[m] + 0.5*Za[m][k]
__global__ void k_sgemm_mix(const float* __restrict__ Za, const float* __restrict__ B,
                            float* __restrict__ C, int offF) {
    __shared__ float As[8][128];
    __shared__ float Bs[8][64];
    int tid = threadIdx.x;
    int tx = tid & 15, ty = tid >> 4;
    int m0 = blockIdx.y*128, n0 = blockIdx.x*64;
    float acc[8][4];
    #pragma unroll
    for (int i=0;i<8;i++)
        #pragma unroll
        for (int j=0;j<4;j++) acc[i][j]=0.f;

    int a_m = tid >> 1;          // 0..127
    int a_k = (tid & 1) * 4;     // 0 or 4
    int b_k = tid >> 5;
    int b_n = (tid & 31) * 2;
    int m = m0 + a_m;
    bool mok = (m < NN);
    float inv = mok ? 0.5f / fmaxf(g_cnt[m], 1.0f) : 0.f;
    const float* poolRow = g_pool + (size_t)(mok ? m : 0)*NPOOL + offF;
    const float* zaRow   = Za     + (size_t)(mok ? m : 0)*CC;

    for (int kt = 0; kt < CC; kt += 8) {
        float4 av = make_float4(0.f,0.f,0.f,0.f);
        if (mok) {
            float4 hp = *reinterpret_cast<const float4*>(poolRow + kt + a_k);
            float4 za = *reinterpret_cast<const float4*>(zaRow   + kt + a_k);
            av.x = hp.x*inv + 0.5f*za.x; av.y = hp.y*inv + 0.5f*za.y;
            av.z = hp.z*inv + 0.5f*za.z; av.w = hp.w*inv + 0.5f*za.w;
        }
        As[a_k+0][a_m]=av.x; As[a_k+1][a_m]=av.y;
        As[a_k+2][a_m]=av.z; As[a_k+3][a_m]=av.w;
        float2 bv = *reinterpret_cast<const float2*>(B + (size_t)(kt+b_k)*CC + n0 + b_n);
        Bs[b_k][b_n]=bv.x; Bs[b_k][b_n+1]=bv.y;
        __syncthreads();
        #pragma unroll
        for (int k = 0; k < 8; k++) {
            float ar[8], br[4];
            #pragma unroll
            for (int i=0;i<8;i++) ar[i]=As[k][ty*8+i];
            #pragma unroll
            for (int j=0;j<4;j++) br[j]=Bs[k][tx*4+j];
            #pragma unroll
            for (int i=0;i<8;i++)
                #pragma unroll
                for (int j=0;j<4;j++) acc[i][j] = fmaf(ar[i], br[j], acc[i][j]);
        }
        __syncthreads();
    }
    #pragma unroll
    for (int i = 0; i < 8; i++) {
        int mm = m0 + ty*8 + i;
        if (mm < NN) {
            #pragma unroll
            for (int j = 0; j < 4; j++)
                C[(size_t)mm*CC + n0 + tx*4 + j] = acc[i][j];
        }
    }
}

// ---------------- epilogue ----------------
__global__ void k_norm_lin(const float* __restrict__ lin_w) {  // one block, 256 thr
    __shared__ float red[8];
    int c = threadIdx.x, lane = c & 31, w = c >> 5;
    for (int k = 0; k < 15; k++) {
        float v = lin_w[k*CC + c];
        float sq = v*v;
        #pragma unroll
        for (int o = 16; o > 0; o >>= 1) sq += __shfl_xor_sync(0xffffffffu, sq, o);
        if (lane == 0) red[w] = sq;
        __syncthreads();
        float tot = 0.f;
        #pragma unroll
        for (int i = 0; i < 8; i++) tot += red[i];
        g_wn[k*CC + c] = v / sqrtf(tot);
        __syncthreads();
    }
}

__global__ void k_out(const float* __restrict__ Z, float* __restrict__ outp) {
    __shared__ float sh[CC];
    __shared__ float red[8];
    int n = blockIdx.x, c = threadIdx.x;
    int lane = c & 31, w = c >> 5;
    float z = Z[(size_t)n*CC + c];
    float sq = z*z;
    #pragma unroll
    for (int o = 16; o > 0; o >>= 1) sq += __shfl_xor_sync(0xffffffffu, sq, o);
    if (lane == 0) red[w] = sq;
    __syncthreads();
    float tot = 0.f;
    #pragma unroll
    for (int i = 0; i < 8; i++) tot += red[i];
    float nrm = fmaxf(sqrtf(tot), 1e-12f);
    float v = z / nrm;
    outp[(size_t)NN*15 + (size_t)n*CC + c] = v;   // cs_r
    sh[c] = v;
    __syncthreads();
    for (int k = w; k < 15; k += 8) {
        float d = 0.f;
        for (int i = lane; i < CC; i += 32) d = fmaf(sh[i], g_wn[k*CC + i], d);
        #pragma unroll
        for (int o = 16; o > 0; o >>= 1) d += __shfl_xor_sync(0xffffffffu, d, o);
        if (lane == 0) outp[(size_t)n*15 + k] = d;   // cs
    }
}

// ---------------- launch ----------------
extern "C" void kernel_launch(void* const* d_in, const int* in_sizes, int n_in,
                              void* d_out, int out_size) {
    const float* image  = (const float*)d_in[0];
    const int*   labels = (const int*)  d_in[1];
    const int*   edges  = (const int*)  d_in[2];
    const float* probas = (const float*)d_in[3];
    const float* feats0 = (const float*)d_in[4];
    const float* feats1 = (const float*)d_in[5];
    const float* W0     = (const float*)d_in[6];
    const float* b0     = (const float*)d_in[7];
    const float* W1     = (const float*)d_in[8];
    const float* b1     = (const float*)d_in[9];
    const float* W2     = (const float*)d_in[10];
    const float* b2     = (const float*)d_in[11];
    const float* lin_w  = (const float*)d_in[12];
    float* outp = (float*)d_out;

    float *pZa, *pXw;
    cudaGetSymbolAddress((void**)&pZa, g_Za);
    cudaGetSymbolAddress((void**)&pXw, g_xw);

    // 1-4: init + pooling build (launch #4 = k_build2, lands in ncu window)
    k_init<<<(NN+255)/256, 256>>>();
    k_build1<<<HWPX/256, 256>>>(labels, image);
    k_scanP<<<1, 1024>>>();
    k_build2<<<HWPX/256, 256>>>(labels);
    // 5-6: transpose + heavy SpMM
    k_transpose<<<dim3(HWI/32, CC/32, 8), dim3(32, 8)>>>(feats0, feats1);
    k_spmm<<<NN, 256>>>();
    // 7-9: graph build
    k_edge_w_deg<<<(EE+255)/256, 256>>>(edges, probas);
    k_scanE<<<1, 1024>>>();
    k_edge_scatter<<<(EE+NN+255)/256, 256>>>(edges);
    // 10: epilogue prep (independent; fills bubble)
    k_norm_lin<<<1, CC>>>(lin_w);
    // 11-12: layer 1 (image)
    k_x0<<<NN, CC>>>(W0);
    k_agg_relu<<<NN/4, 256>>>(pXw, b0, pZa);
    // 13-14: layer 2 (feats0) — mix fused into GEMM
    k_sgemm_mix<<<dim3(CC/64, (NN+127)/128), 256>>>(pZa, W1, pXw, 0);
    k_agg_relu<<<NN/4, 256>>>(pXw, b1, pZa);
    // 15-16: layer 3 (feats1)
    k_sgemm_mix<<<dim3(CC/64, (NN+127)/128), 256>>>(pZa, W2, pXw, CC);
    k_agg_relu<<<NN/4, 256>>>(pXw, b2, pZa);
    // 17: output
    k_out<<<NN, CC>>>(pZa, outp);
    (void)in_sizes; (void)n_in; (void)out_size;
}

// round 15
// speedup vs baseline: 1.6798x; 1.0949x over previous
#include <cuda_runtime.h>
#include <cuda_fp16.h>
#include <math.h>
#include <stdint.h>

// ---------------- problem constants ----------------
#define BB   4
#define NSP  1500
#define NN   6000          // BB*NSP
#define N4   (NN*4)        // sharded counters (4 shards per superpixel)
#define EE   120000
#define HH   384
#define HWPX (HH*HH)       // 147456
#define NPX  (BB*HWPX)     // 589824
#define HS   96
#define HWI  (HS*HS)       // 9216
#define CC   256
#define NPOOL 512          // feats0 | feats1 columns
#define NENT (2*NPX)       // 1179648 pair-compressed pooling entries
#define CSR_E (EE+NN)      // folded self loops: one entry each, weight 2*dis^2
#define SIGMA_INV 5.0f     // 1/0.2

// fused-kernel block ranges
#define B1_BLK (HWPX/256)          // 576  build1
#define ED_BLK ((EE+255)/256)      // 469  edge_w_deg
#define TR_BLK (288*8*8)           // 18432 transpose
#define B2_BLK (HWPX/256)          // 576  build2
#define SC_BLK ((EE+NN+255)/256)   // 493  edge_scatter

// ---------------- scratch (device globals; k_init re-inits every call) ----------
__device__ __half g_Bmh[(size_t)BB*HWI*NPOOL + NPOOL]; // 37.7 MB + 1 pad row
__device__ int4  g_ent4[NENT/2];                 // (q,w2,q,w2) pairs, 9.4 MB
__device__ float g_pool[(size_t)NN*NPOOL];
__device__ float g_Za[NN*CC];
__device__ float g_xw[NN*CC];
__device__ float g_cnt[NN];
__device__ float g_sumI4[N4*3];  // sharded image sums
__device__ float g_deg[NN];      // self-loop +2 folded into dis computation
__device__ float g_dis[NN];
__device__ float g_wnn[EE];
__device__ int   g_picnt[N4];    // sharded pooling counts
__device__ int   g_pfill4[N4];   // sharded fill cursors
__device__ int   g_poff4[N4+1];  // sharded offsets; s's range = [4s, 4s+4)
__device__ int   g_ecnt[NN];     // +1 self slot folded into scanE
__device__ int   g_eoff[NN+1];
__device__ int   g_efill[NN];
__device__ int   g_csr_src[CSR_E];
__device__ float g_csr_nrm[CSR_E];
__device__ float g_wn[15*CC];

// ---------------- 0: init (self-healing regardless of prior stream state) -------
__global__ void k_init() {
    int i = blockIdx.x*blockDim.x + threadIdx.x;
    if (i >= NN) return;
    g_ecnt[i] = 0; g_efill[i] = 0;
    g_deg[i] = 0.f;
    #pragma unroll
    for (int k = 0; k < 4; k++) {
        g_picnt[i*4+k] = 0; g_pfill4[i*4+k] = 0;
        g_sumI4[(i*4+k)*3+0] = 0.f;
        g_sumI4[(i*4+k)*3+1] = 0.f;
        g_sumI4[(i*4+k)*3+2] = 0.f;
    }
}

// ---------------- 1 (fused): build1 | edge_w_deg | transpose ---------------------
__global__ void k_fuse1(const int* __restrict__ labels, const float* __restrict__ image,
                        const int* __restrict__ edges, const float* __restrict__ probas,
                        const float* __restrict__ f0, const float* __restrict__ f1) {
    __shared__ float t[32][33];
    int blk = blockIdx.x, tid = threadIdx.x;

    if (blk < B1_BLK) {
        // ---- build1: sharded counts + image sums ----
        int yx = blk*256 + tid;
        int shard = yx & 3;
        #pragma unroll
        for (int b = 0; b < BB; b++) {
            int s = b*NSP + labels[b*HWPX + yx];
            int cidx = s*4 + shard;
            atomicAdd(&g_picnt[cidx], 1);
            #pragma unroll
            for (int c = 0; c < 3; c++)
                atomicAdd(&g_sumI4[cidx*3+c], image[(size_t)(b*3+c)*HWPX + yx]);
        }
        return;
    }
    if (blk < B1_BLK + ED_BLK) {
        // ---- edge weights + degree + per-dst counts ----
        int e = (blk - B1_BLK)*256 + tid;
        if (e >= EE) return;
        int src = edges[e], dst = edges[EE + e];
        float w = expf(-fabsf(probas[src] - probas[dst]) * SIGMA_INV);
        g_wnn[e] = w;
        atomicAdd(&g_deg[dst], w);
        atomicAdd(&g_ecnt[dst], 1);
        return;
    }
    {
        // ---- feats transpose NCHW -> fp16 (b*9216, 512) ----
        int z3 = blk - (B1_BLK + ED_BLK);     // 0..18431
        int qb = z3 % 288; z3 /= 288;
        int cb = z3 % 8;   int z = z3 / 8;    // z: 0..7
        int b = z & 3;
        int colOff = (z >> 2) * CC;
        const float* __restrict__ src = (z < 4) ? f0 : f1;
        int q0 = qb*32, c0 = cb*32;
        int tx = tid & 31, ty = tid >> 5;     // 32 x 8
        #pragma unroll
        for (int i = 0; i < 32; i += 8) {
            int c = c0 + ty + i, q = q0 + tx;
            t[ty+i][tx] = src[((size_t)b*CC + c)*HWI + q];
        }
        __syncthreads();
        int qrow = tid >> 3, cg = tid & 7;
        __half2 h0 = __floats2half2_rn(t[cg*4+0][qrow], t[cg*4+1][qrow]);
        __half2 h1 = __floats2half2_rn(t[cg*4+2][qrow], t[cg*4+3][qrow]);
        uint2 o;
        o.x = *reinterpret_cast<unsigned*>(&h0);
        o.y = *reinterpret_cast<unsigned*>(&h1);
        size_t base = ((size_t)b*HWI + q0 + qrow)*NPOOL + colOff + c0 + cg*4;
        *reinterpret_cast<uint2*>(&g_Bmh[base]) = o;
    }
}

// ---------------- 2 (fused): scanP | scanE | norm_lin ---------------------------
__global__ void k_scan2(const float* __restrict__ lin_w) {
    __shared__ int wsum[32];
    __shared__ float red[8];
    int t = threadIdx.x, lane = t & 31, w = t >> 5;

    if (blockIdx.x == 0) {
        // ---- scanP: 24000 sharded counts (x2) + cnt ----
        int loc[24]; int s = 0;
        #pragma unroll
        for (int i = 0; i < 24; i++) {
            int idx = t*24 + i;
            int v = (idx < N4) ? 2*g_picnt[idx] : 0;
            loc[i] = s; s += v;
        }
        #pragma unroll
        for (int g = 0; g < 6; g++) {
            int sp = t*6 + g;
            if (sp < NN)
                g_cnt[sp] = (float)(g_picnt[4*sp] + g_picnt[4*sp+1]
                                  + g_picnt[4*sp+2] + g_picnt[4*sp+3]);
        }
        int x = s;
        #pragma unroll
        for (int o = 1; o < 32; o <<= 1) {
            int y = __shfl_up_sync(0xffffffffu, x, o);
            if (lane >= o) x += y;
        }
        if (lane == 31) wsum[w] = x;
        __syncthreads();
        if (w == 0) {
            int y = wsum[lane];
            #pragma unroll
            for (int o = 1; o < 32; o <<= 1) {
                int z2 = __shfl_up_sync(0xffffffffu, y, o);
                if (lane >= o) y += z2;
            }
            wsum[lane] = y;
        }
        __syncthreads();
        int base = (w > 0 ? wsum[w-1] : 0) + x - s;
        #pragma unroll
        for (int i = 0; i < 24; i++) {
            int idx = t*24 + i;
            if (idx < N4) g_poff4[idx] = base + loc[i];
        }
        if (t == 1023) g_poff4[N4] = base + s;
    } else if (blockIdx.x == 1) {
        // ---- scanE: edge counts (+1 self slot) + dis ----
        int loc[6]; int s = 0;
        #pragma unroll
        for (int i = 0; i < 6; i++) {
            int idx = t*6 + i;
            int v = (idx < NN) ? (g_ecnt[idx] + 1) : 0;
            loc[i] = s; s += v;
            if (idx < NN) {
                float d = g_deg[idx] + 2.0f;
                g_dis[idx] = rsqrtf(fmaxf(d, 1e-30f));
            }
        }
        int x = s;
        #pragma unroll
        for (int o = 1; o < 32; o <<= 1) {
            int y = __shfl_up_sync(0xffffffffu, x, o);
            if (lane >= o) x += y;
        }
        if (lane == 31) wsum[w] = x;
        __syncthreads();
        if (w == 0) {
            int y = wsum[lane];
            #pragma unroll
            for (int o = 1; o < 32; o <<= 1) {
                int z2 = __shfl_up_sync(0xffffffffu, y, o);
                if (lane >= o) y += z2;
            }
            wsum[lane] = y;
        }
        __syncthreads();
        int base = (w > 0 ? wsum[w-1] : 0) + x - s;
        #pragma unroll
        for (int i = 0; i < 6; i++) {
            int idx = t*6 + i;
            if (idx < NN) g_eoff[idx] = base + loc[i];
        }
        if (t == 1023) g_eoff[NN] = base + s;
    } else {
        // ---- norm_lin (duplicated across 4 thread groups; identical values) ----
        int c = t & 255;
        int l2 = c & 31, w2 = c >> 5;
        for (int k = 0; k < 15; k++) {
            float v = lin_w[k*CC + c];
            float sq = v*v;
            #pragma unroll
            for (int o = 16; o > 0; o >>= 1) sq += __shfl_xor_sync(0xffffffffu, sq, o);
            if (l2 == 0) red[w2] = sq;
            __syncthreads();
            float tot = 0.f;
            #pragma unroll
            for (int i = 0; i < 8; i++) tot += red[i];
            g_wn[k*CC + c] = v / sqrtf(tot);
            __syncthreads();
        }
    }
}

// ---------------- 3 (fused): build2 | edge_scatter | x0 -------------------------
__global__ void k_fuse2(const int* __restrict__ labels, const int* __restrict__ edges,
                        const float* __restrict__ W0) {
    __shared__ float z0[3];
    int blk = blockIdx.x, tid = threadIdx.x;

    if (blk < B2_BLK) {
        // ---- build2: pooling entries (sharded cursors) ----
        int yx = blk*256 + tid;
        int shard = yx & 3;
        int y = yx / HH, x = yx % HH;
        const float scale = 95.0f/383.0f;
        float fy = y*scale, fx = x*scale;
        int y0 = (int)floorf(fy); if (y0 > 95) y0 = 95;
        int x0 = (int)floorf(fx); if (x0 > 95) x0 = 95;
        float wy = fy - y0, wx = fx - x0;
        int y1 = min(y0+1, 95);
        float w00 = (1.f-wy)*(1.f-wx), w01 = (1.f-wy)*wx;
        float w10 = wy*(1.f-wx),       w11 = wy*wx;
        if (x0 == 95) { w00 += w01; w01 = 0.f; w10 += w11; w11 = 0.f; }
        __half2 wt = __floats2half2_rn(w00, w01);
        __half2 wb = __floats2half2_rn(w10, w11);
        int wti = *reinterpret_cast<int*>(&wt);
        int wbi = *reinterpret_cast<int*>(&wb);
        int qt = y0*HS + x0, qb = y1*HS + x0;
        #pragma unroll
        for (int b = 0; b < BB; b++) {
            int s = b*NSP + labels[b*HWPX + yx];
            int cidx = s*4 + shard;
            int pos = g_poff4[cidx] + atomicAdd(&g_pfill4[cidx], 2);
            int4 e;
            e.x = b*HWI + qt;  e.y = wti;
            e.z = b*HWI + qb;  e.w = wbi;
            g_ent4[pos>>1] = e;
        }
        return;
    }
    if (blk < B2_BLK + SC_BLK) {
        // ---- edge CSR scatter (self loop -> last slot) ----
        int i = (blk - B2_BLK)*256 + tid;
        if (i >= EE + NN) return;
        if (i < EE) {
            int src = edges[i], dst = edges[EE + i];
            float w = g_wnn[i];
            int j = g_eoff[dst] + atomicAdd(&g_efill[dst], 1);
            g_csr_src[j] = src;
            g_csr_nrm[j] = g_dis[src] * w * g_dis[dst];
        } else {
            int n = i - EE;
            int j = g_eoff[n+1] - 1;
            g_csr_src[j] = n;
            g_csr_nrm[j] = 2.0f * g_dis[n] * g_dis[n];
        }
        return;
    }
    {
        // ---- x0: xw = (sumI/cnt) @ W0 (K=3) ----
        int n = blk - (B2_BLK + SC_BLK);
        int c = tid;
        if (c < 3) {
            float v = g_sumI4[(n*4+0)*3+c] + g_sumI4[(n*4+1)*3+c]
                    + g_sumI4[(n*4+2)*3+c] + g_sumI4[(n*4+3)*3+c];
            z0[c] = v / fmaxf(g_cnt[n], 1.0f);
        }
        __syncthreads();
        g_xw[(size_t)n*CC + c] = z0[0]*W0[c] + z0[1]*W0[CC+c] + z0[2]*W0[2*CC+c];
    }
}

// ---------------- 4: sparse pooling SpMM (pair entries) ----------------
__device__ __forceinline__ void acc8(float* acc, float w, uint4 v) {
    float2 f0 = __half22float2(*(const __half2*)&v.x);
    float2 f1 = __half22float2(*(const __half2*)&v.y);
    float2 f2 = __half22float2(*(const __half2*)&v.z);
    float2 f3 = __half22float2(*(const __half2*)&v.w);
    acc[0] = fmaf(w, f0.x, acc[0]); acc[1] = fmaf(w, f0.y, acc[1]);
    acc[2] = fmaf(w, f1.x, acc[2]); acc[3] = fmaf(w, f1.y, acc[3]);
    acc[4] = fmaf(w, f2.x, acc[4]); acc[5] = fmaf(w, f2.y, acc[5]);
    acc[6] = fmaf(w, f3.x, acc[6]); acc[7] = fmaf(w, f3.y, acc[7]);
}

__global__ void k_spmm() {
    __shared__ int2  sh[256];
    __shared__ float red[4][512];
    int s = blockIdx.x;
    int tid = threadIdx.x;
    int team = tid >> 6, lane = tid & 63;
    int beg = g_poff4[4*s], end = g_poff4[4*s+4];
    const uint4* __restrict__ B4 = reinterpret_cast<const uint4*>(g_Bmh);
    const int2* __restrict__ ent = reinterpret_cast<const int2*>(g_ent4);
    float acc[8];
    #pragma unroll
    for (int i = 0; i < 8; i++) acc[i] = 0.f;

    for (int c0 = beg; c0 < end; c0 += 256) {
        int m = min(256, end - c0);
        __syncthreads();
        if (tid < m) sh[tid] = ent[c0 + tid];
        __syncthreads();
        for (int j = team; j < m; j += 4) {
            int2 e = sh[j];
            float2 wv = __half22float2(*reinterpret_cast<__half2*>(&e.y));
            size_t r = (size_t)e.x*64 + lane;
            uint4 vlo = B4[r];
            uint4 vhi = B4[r + 64];
            acc8(acc, wv.x, vlo);
            acc8(acc, wv.y, vhi);
        }
    }
    #pragma unroll
    for (int i = 0; i < 8; i++) red[team][lane*8+i] = acc[i];
    __syncthreads();
    #pragma unroll
    for (int c = tid; c < 512; c += 256)
        g_pool[(size_t)s*NPOOL + c] = red[0][c] + red[1][c] + red[2][c] + red[3][c];
}

// ---------------- agg_relu: 4 teams x 64 lanes, float4, 2-way unroll ------------
__global__ void k_agg_relu(const float* __restrict__ xw, const float* __restrict__ bias,
                           float* __restrict__ out) {
    int tid = threadIdx.x;
    int team = tid >> 6, lane = tid & 63;
    int n = blockIdx.x*4 + team;
    const float4* __restrict__ xw4 = reinterpret_cast<const float4*>(xw);
    float4 bv = reinterpret_cast<const float4*>(bias)[lane];
    int s = g_eoff[n], e = g_eoff[n+1];
    float4 a0 = make_float4(0.f,0.f,0.f,0.f);
    float4 a1 = make_float4(0.f,0.f,0.f,0.f);
    int j = s;
    for (; j + 1 < e; j += 2) {
        int   sc0 = __ldg(&g_csr_src[j]);
        int   sc1 = __ldg(&g_csr_src[j+1]);
        float nr0 = __ldg(&g_csr_nrm[j]);
        float nr1 = __ldg(&g_csr_nrm[j+1]);
        float4 v0 = xw4[(size_t)sc0*64 + lane];
        float4 v1 = xw4[(size_t)sc1*64 + lane];
        a0.x = fmaf(nr0, v0.x, a0.x); a0.y = fmaf(nr0, v0.y, a0.y);
        a0.z = fmaf(nr0, v0.z, a0.z); a0.w = fmaf(nr0, v0.w, a0.w);
        a1.x = fmaf(nr1, v1.x, a1.x); a1.y = fmaf(nr1, v1.y, a1.y);
        a1.z = fmaf(nr1, v1.z, a1.z); a1.w = fmaf(nr1, v1.w, a1.w);
    }
    if (j < e) {
        int   sc0 = __ldg(&g_csr_src[j]);
        float nr0 = __ldg(&g_csr_nrm[j]);
        float4 v0 = xw4[(size_t)sc0*64 + lane];
        a0.x = fmaf(nr0, v0.x, a0.x); a0.y = fmaf(nr0, v0.y, a0.y);
        a0.z = fmaf(nr0, v0.z, a0.z); a0.w = fmaf(nr0, v0.w, a0.w);
    }
    float4 r;
    r.x = fmaxf(a0.x + a1.x + bv.x, 0.f); r.y = fmaxf(a0.y + a1.y + bv.y, 0.f);
    r.z = fmaxf(a0.z + a1.z + bv.z, 0.f); r.w = fmaxf(a0.w + a1.w + bv.w, 0.f);
    reinterpret_cast<float4*>(out)[(size_t)n*64 + lane] = r;
}

// ---------------- SGEMM with fused mix A-operand ----------------
__global__ void k_sgemm_mix(const float* __restrict__ Za, const float* __restrict__ B,
                            float* __restrict__ C, int offF) {
    __shared__ float As[8][128];
    __shared__ float Bs[8][64];
    int tid = threadIdx.x;
    int tx = tid & 15, ty = tid >> 4;
    int m0 = blockIdx.y*128, n0 = blockIdx.x*64;
    float acc[8][4];
    #pragma unroll
    for (int i=0;i<8;i++)
        #pragma unroll
        for (int j=0;j<4;j++) acc[i][j]=0.f;

    int a_m = tid >> 1;
    int a_k = (tid & 1) * 4;
    int b_k = tid >> 5;
    int b_n = (tid & 31) * 2;
    int m = m0 + a_m;
    bool mok = (m < NN);
    float inv = mok ? 0.5f / fmaxf(g_cnt[m], 1.0f) : 0.f;
    const float* poolRow = g_pool + (size_t)(mok ? m : 0)*NPOOL + offF;
    const float* zaRow   = Za     + (size_t)(mok ? m : 0)*CC;

    for (int kt = 0; kt < CC; kt += 8) {
        float4 av = make_float4(0.f,0.f,0.f,0.f);
        if (mok) {
            float4 hp = *reinterpret_cast<const float4*>(poolRow + kt + a_k);
            float4 za = *reinterpret_cast<const float4*>(zaRow   + kt + a_k);
            av.x = hp.x*inv + 0.5f*za.x; av.y = hp.y*inv + 0.5f*za.y;
            av.z = hp.z*inv + 0.5f*za.z; av.w = hp.w*inv + 0.5f*za.w;
        }
        As[a_k+0][a_m]=av.x; As[a_k+1][a_m]=av.y;
        As[a_k+2][a_m]=av.z; As[a_k+3][a_m]=av.w;
        float2 bv = *reinterpret_cast<const float2*>(B + (size_t)(kt+b_k)*CC + n0 + b_n);
        Bs[b_k][b_n]=bv.x; Bs[b_k][b_n+1]=bv.y;
        __syncthreads();
        #pragma unroll
        for (int k = 0; k < 8; k++) {
            float ar[8], br[4];
            #pragma unroll
            for (int i=0;i<8;i++) ar[i]=As[k][ty*8+i];
            #pragma unroll
            for (int j=0;j<4;j++) br[j]=Bs[k][tx*4+j];
            #pragma unroll
            for (int i=0;i<8;i++)
                #pragma unroll
                for (int j=0;j<4;j++) acc[i][j] = fmaf(ar[i], br[j], acc[i][j]);
        }
        __syncthreads();
    }
    #pragma unroll
    for (int i = 0; i < 8; i++) {
        int mm = m0 + ty*8 + i;
        if (mm < NN) {
            #pragma unroll
            for (int j = 0; j < 4; j++)
                C[(size_t)mm*CC + n0 + tx*4 + j] = acc[i][j];
        }
    }
}

// ---------------- output ----------------
__global__ void k_out(const float* __restrict__ Z, float* __restrict__ outp) {
    __shared__ float sh[CC];
    __shared__ float red[8];
    int n = blockIdx.x, c = threadIdx.x;
    int lane = c & 31, w = c >> 5;
    float z = Z[(size_t)n*CC + c];
    float sq = z*z;
    #pragma unroll
    for (int o = 16; o > 0; o >>= 1) sq += __shfl_xor_sync(0xffffffffu, sq, o);
    if (lane == 0) red[w] = sq;
    __syncthreads();
    float tot = 0.f;
    #pragma unroll
    for (int i = 0; i < 8; i++) tot += red[i];
    float nrm = fmaxf(sqrtf(tot), 1e-12f);
    float v = z / nrm;
    outp[(size_t)NN*15 + (size_t)n*CC + c] = v;   // cs_r
    sh[c] = v;
    __syncthreads();
    for (int k = w; k < 15; k += 8) {
        float d = 0.f;
        for (int i = lane; i < CC; i += 32) d = fmaf(sh[i], g_wn[k*CC + i], d);
        #pragma unroll
        for (int o = 16; o > 0; o >>= 1) d += __shfl_xor_sync(0xffffffffu, d, o);
        if (lane == 0) outp[(size_t)n*15 + k] = d;   // cs
    }
}

// ---------------- launch ----------------
extern "C" void kernel_launch(void* const* d_in, const int* in_sizes, int n_in,
                              void* d_out, int out_size) {
    const float* image  = (const float*)d_in[0];
    const int*   labels = (const int*)  d_in[1];
    const int*   edges  = (const int*)  d_in[2];
    const float* probas = (const float*)d_in[3];
    const float* feats0 = (const float*)d_in[4];
    const float* feats1 = (const float*)d_in[5];
    const float* W0     = (const float*)d_in[6];
    const float* b0     = (const float*)d_in[7];
    const float* W1     = (const float*)d_in[8];
    const float* b1     = (const float*)d_in[9];
    const float* W2     = (const float*)d_in[10];
    const float* b2     = (const float*)d_in[11];
    const float* lin_w  = (const float*)d_in[12];
    float* outp = (float*)d_out;

    float *pZa, *pXw;
    cudaGetSymbolAddress((void**)&pZa, g_Za);
    cudaGetSymbolAddress((void**)&pXw, g_xw);

    // 1-4: init, fused build/edge/transpose, fused scans, fused build2/scatter/x0
    k_init<<<(NN+255)/256, 256>>>();
    k_fuse1<<<B1_BLK + ED_BLK + TR_BLK, 256>>>(labels, image, edges, probas, feats0, feats1);
    k_scan2<<<3, 1024>>>(lin_w);
    k_fuse2<<<B2_BLK + SC_BLK + NN, 256>>>(labels, edges, W0);
    // 5: heavy SpMM
    k_spmm<<<NN, 256>>>();
    // 6: layer 1 aggregation
    k_agg_relu<<<NN/4, 256>>>(pXw, b0, pZa);
    // 7-8: layer 2 (feats0)
    k_sgemm_mix<<<dim3(CC/64, (NN+127)/128), 256>>>(pZa, W1, pXw, 0);
    k_agg_relu<<<NN/4, 256>>>(pXw, b1, pZa);
    // 9-10: layer 3 (feats1)
    k_sgemm_mix<<<dim3(CC/64, (NN+127)/128), 256>>>(pZa, W2, pXw, CC);
    k_agg_relu<<<NN/4, 256>>>(pXw, b2, pZa);
    // 11: output
    k_out<<<NN, CC>>>(pZa, outp);
    (void)in_sizes; (void)n_in; (void)out_size;
}

// round 16
// speedup vs baseline: 1.7568x; 1.0458x over previous
#include <cuda_runtime.h>
#include <cuda_fp16.h>
#include <math.h>
#include <stdint.h>

// ---------------- problem constants ----------------
#define BB   4
#define NSP  1500
#define NN   6000          // BB*NSP
#define N4   (NN*4)        // sharded counters (4 shards per superpixel)
#define EE   120000
#define HH   384
#define HWPX (HH*HH)       // 147456
#define NPX  (BB*HWPX)     // 589824
#define HS   96
#define HWI  (HS*HS)       // 9216
#define CC   256
#define NPOOL 512          // feats0 | feats1 columns
#define NENT (2*NPX)       // 1179648 pair-compressed pooling entries
#define CSR_E (EE+NN)      // folded self loops: one entry each, weight 2*dis^2
#define SIGMA_INV 5.0f     // 1/0.2

// fused-kernel block ranges
#define B1_BLK (HWPX/256)          // 576  build1
#define ED_BLK ((EE+255)/256)      // 469  edge_w_deg
#define TR_BLK (288*8*8)           // 18432 transpose
#define B2_BLK (HWPX/256)          // 576  build2
#define SC_BLK ((EE+NN+255)/256)   // 493  edge_scatter
#define SP_BLK NN                  // 6000 spmm
#define AG_BLK (NN/4)              // 1500 agg layer-1

// ---------------- scratch (device globals; k_init re-inits every call) ----------
__device__ __half g_Bmh[(size_t)BB*HWI*NPOOL + NPOOL]; // 37.7 MB + 1 pad row
__device__ int4  g_ent4[NENT/2];                 // (q,w2,q,w2) pairs, 9.4 MB
__device__ float g_pool[(size_t)NN*NPOOL];
__device__ float g_Za[NN*CC];
__device__ float g_xw[NN*CC];
__device__ float g_cnt[NN];
__device__ float g_sumI4[N4*3];  // sharded image sums
__device__ float g_deg[NN];      // self-loop +2 folded into dis computation
__device__ float g_dis[NN];
__device__ float g_wnn[EE];
__device__ int   g_picnt[N4];    // sharded pooling counts
__device__ int   g_pfill4[N4];   // sharded fill cursors
__device__ int   g_poff4[N4+1];  // sharded offsets; s's range = [4s, 4s+4)
__device__ int   g_ecnt[NN];     // +1 self slot folded into scanE
__device__ int   g_eoff[NN+1];
__device__ int   g_efill[NN];
__device__ int   g_csr_src[CSR_E];
__device__ float g_csr_nrm[CSR_E];
__device__ float g_wn[15*CC];

// ---------------- 0: init (self-healing regardless of prior stream state) -------
__global__ void k_init() {
    int i = blockIdx.x*blockDim.x + threadIdx.x;
    if (i >= NN) return;
    g_ecnt[i] = 0; g_efill[i] = 0;
    g_deg[i] = 0.f;
    #pragma unroll
    for (int k = 0; k < 4; k++) {
        g_picnt[i*4+k] = 0; g_pfill4[i*4+k] = 0;
        g_sumI4[(i*4+k)*3+0] = 0.f;
        g_sumI4[(i*4+k)*3+1] = 0.f;
        g_sumI4[(i*4+k)*3+2] = 0.f;
    }
}

// ---------------- 1 (fused): build1 | edge_w_deg | transpose ---------------------
__global__ void k_fuse1(const int* __restrict__ labels, const float* __restrict__ image,
                        const int* __restrict__ edges, const float* __restrict__ probas,
                        const float* __restrict__ f0, const float* __restrict__ f1) {
    __shared__ float t[32][33];
    int blk = blockIdx.x, tid = threadIdx.x;

    if (blk < B1_BLK) {
        int yx = blk*256 + tid;
        int shard = yx & 3;
        #pragma unroll
        for (int b = 0; b < BB; b++) {
            int s = b*NSP + labels[b*HWPX + yx];
            int cidx = s*4 + shard;
            atomicAdd(&g_picnt[cidx], 1);
            #pragma unroll
            for (int c = 0; c < 3; c++)
                atomicAdd(&g_sumI4[cidx*3+c], image[(size_t)(b*3+c)*HWPX + yx]);
        }
        return;
    }
    if (blk < B1_BLK + ED_BLK) {
        int e = (blk - B1_BLK)*256 + tid;
        if (e >= EE) return;
        int src = edges[e], dst = edges[EE + e];
        float w = expf(-fabsf(probas[src] - probas[dst]) * SIGMA_INV);
        g_wnn[e] = w;
        atomicAdd(&g_deg[dst], w);
        atomicAdd(&g_ecnt[dst], 1);
        return;
    }
    {
        int z3 = blk - (B1_BLK + ED_BLK);     // 0..18431
        int qb = z3 % 288; z3 /= 288;
        int cb = z3 % 8;   int z = z3 / 8;    // z: 0..7
        int b = z & 3;
        int colOff = (z >> 2) * CC;
        const float* __restrict__ src = (z < 4) ? f0 : f1;
        int q0 = qb*32, c0 = cb*32;
        int tx = tid & 31, ty = tid >> 5;     // 32 x 8
        #pragma unroll
        for (int i = 0; i < 32; i += 8) {
            int c = c0 + ty + i, q = q0 + tx;
            t[ty+i][tx] = src[((size_t)b*CC + c)*HWI + q];
        }
        __syncthreads();
        int qrow = tid >> 3, cg = tid & 7;
        __half2 h0 = __floats2half2_rn(t[cg*4+0][qrow], t[cg*4+1][qrow]);
        __half2 h1 = __floats2half2_rn(t[cg*4+2][qrow], t[cg*4+3][qrow]);
        uint2 o;
        o.x = *reinterpret_cast<unsigned*>(&h0);
        o.y = *reinterpret_cast<unsigned*>(&h1);
        size_t base = ((size_t)b*HWI + q0 + qrow)*NPOOL + colOff + c0 + cg*4;
        *reinterpret_cast<uint2*>(&g_Bmh[base]) = o;
    }
}

// ---------------- 2 (fused): scanP | scanE | norm_lin ---------------------------
__global__ void k_scan2(const float* __restrict__ lin_w) {
    __shared__ int wsum[32];
    __shared__ float red[8];
    int t = threadIdx.x, lane = t & 31, w = t >> 5;

    if (blockIdx.x == 0) {
        int loc[24]; int s = 0;
        #pragma unroll
        for (int i = 0; i < 24; i++) {
            int idx = t*24 + i;
            int v = (idx < N4) ? 2*g_picnt[idx] : 0;
            loc[i] = s; s += v;
        }
        #pragma unroll
        for (int g = 0; g < 6; g++) {
            int sp = t*6 + g;
            if (sp < NN)
                g_cnt[sp] = (float)(g_picnt[4*sp] + g_picnt[4*sp+1]
                                  + g_picnt[4*sp+2] + g_picnt[4*sp+3]);
        }
        int x = s;
        #pragma unroll
        for (int o = 1; o < 32; o <<= 1) {
            int y = __shfl_up_sync(0xffffffffu, x, o);
            if (lane >= o) x += y;
        }
        if (lane == 31) wsum[w] = x;
        __syncthreads();
        if (w == 0) {
            int y = wsum[lane];
            #pragma unroll
            for (int o = 1; o < 32; o <<= 1) {
                int z2 = __shfl_up_sync(0xffffffffu, y, o);
                if (lane >= o) y += z2;
            }
            wsum[lane] = y;
        }
        __syncthreads();
        int base = (w > 0 ? wsum[w-1] : 0) + x - s;
        #pragma unroll
        for (int i = 0; i < 24; i++) {
            int idx = t*24 + i;
            if (idx < N4) g_poff4[idx] = base + loc[i];
        }
        if (t == 1023) g_poff4[N4] = base + s;
    } else if (blockIdx.x == 1) {
        int loc[6]; int s = 0;
        #pragma unroll
        for (int i = 0; i < 6; i++) {
            int idx = t*6 + i;
            int v = (idx < NN) ? (g_ecnt[idx] + 1) : 0;
            loc[i] = s; s += v;
            if (idx < NN) {
                float d = g_deg[idx] + 2.0f;
                g_dis[idx] = rsqrtf(fmaxf(d, 1e-30f));
            }
        }
        int x = s;
        #pragma unroll
        for (int o = 1; o < 32; o <<= 1) {
            int y = __shfl_up_sync(0xffffffffu, x, o);
            if (lane >= o) x += y;
        }
        if (lane == 31) wsum[w] = x;
        __syncthreads();
        if (w == 0) {
            int y = wsum[lane];
            #pragma unroll
            for (int o = 1; o < 32; o <<= 1) {
                int z2 = __shfl_up_sync(0xffffffffu, y, o);
                if (lane >= o) y += z2;
            }
            wsum[lane] = y;
        }
        __syncthreads();
        int base = (w > 0 ? wsum[w-1] : 0) + x - s;
        #pragma unroll
        for (int i = 0; i < 6; i++) {
            int idx = t*6 + i;
            if (idx < NN) g_eoff[idx] = base + loc[i];
        }
        if (t == 1023) g_eoff[NN] = base + s;
    } else {
        int c = t & 255;
        int l2 = c & 31, w2 = c >> 5;
        for (int k = 0; k < 15; k++) {
            float v = lin_w[k*CC + c];
            float sq = v*v;
            #pragma unroll
            for (int o = 16; o > 0; o >>= 1) sq += __shfl_xor_sync(0xffffffffu, sq, o);
            if (l2 == 0) red[w2] = sq;
            __syncthreads();
            float tot = 0.f;
            #pragma unroll
            for (int i = 0; i < 8; i++) tot += red[i];
            g_wn[k*CC + c] = v / sqrtf(tot);
            __syncthreads();
        }
    }
}

// ---------------- 3 (fused): build2 | edge_scatter | x0 -------------------------
__global__ void k_fuse2(const int* __restrict__ labels, const int* __restrict__ edges,
                        const float* __restrict__ W0) {
    __shared__ float z0[3];
    int blk = blockIdx.x, tid = threadIdx.x;

    if (blk < B2_BLK) {
        int yx = blk*256 + tid;
        int shard = yx & 3;
        int y = yx / HH, x = yx % HH;
        const float scale = 95.0f/383.0f;
        float fy = y*scale, fx = x*scale;
        int y0 = (int)floorf(fy); if (y0 > 95) y0 = 95;
        int x0 = (int)floorf(fx); if (x0 > 95) x0 = 95;
        float wy = fy - y0, wx = fx - x0;
        int y1 = min(y0+1, 95);
        float w00 = (1.f-wy)*(1.f-wx), w01 = (1.f-wy)*wx;
        float w10 = wy*(1.f-wx),       w11 = wy*wx;
        if (x0 == 95) { w00 += w01; w01 = 0.f; w10 += w11; w11 = 0.f; }
        __half2 wt = __floats2half2_rn(w00, w01);
        __half2 wb = __floats2half2_rn(w10, w11);
        int wti = *reinterpret_cast<int*>(&wt);
        int wbi = *reinterpret_cast<int*>(&wb);
        int qt = y0*HS + x0, qb = y1*HS + x0;
        #pragma unroll
        for (int b = 0; b < BB; b++) {
            int s = b*NSP + labels[b*HWPX + yx];
            int cidx = s*4 + shard;
            int pos = g_poff4[cidx] + atomicAdd(&g_pfill4[cidx], 2);
            int4 e;
            e.x = b*HWI + qt;  e.y = wti;
            e.z = b*HWI + qb;  e.w = wbi;
            g_ent4[pos>>1] = e;
        }
        return;
    }
    if (blk < B2_BLK + SC_BLK) {
        int i = (blk - B2_BLK)*256 + tid;
        if (i >= EE + NN) return;
        if (i < EE) {
            int src = edges[i], dst = edges[EE + i];
            float w = g_wnn[i];
            int j = g_eoff[dst] + atomicAdd(&g_efill[dst], 1);
            g_csr_src[j] = src;
            g_csr_nrm[j] = g_dis[src] * w * g_dis[dst];
        } else {
            int n = i - EE;
            int j = g_eoff[n+1] - 1;
            g_csr_src[j] = n;
            g_csr_nrm[j] = 2.0f * g_dis[n] * g_dis[n];
        }
        return;
    }
    {
        int n = blk - (B2_BLK + SC_BLK);
        int c = tid;
        if (c < 3) {
            float v = g_sumI4[(n*4+0)*3+c] + g_sumI4[(n*4+1)*3+c]
                    + g_sumI4[(n*4+2)*3+c] + g_sumI4[(n*4+3)*3+c];
            z0[c] = v / fmaxf(g_cnt[n], 1.0f);
        }
        __syncthreads();
        g_xw[(size_t)n*CC + c] = z0[0]*W0[c] + z0[1]*W0[CC+c] + z0[2]*W0[2*CC+c];
    }
}

// ---------------- shared device helpers ----------------
__device__ __forceinline__ void acc8(float* acc, float w, uint4 v) {
    float2 f0 = __half22float2(*(const __half2*)&v.x);
    float2 f1 = __half22float2(*(const __half2*)&v.y);
    float2 f2 = __half22float2(*(const __half2*)&v.z);
    float2 f3 = __half22float2(*(const __half2*)&v.w);
    acc[0] = fmaf(w, f0.x, acc[0]); acc[1] = fmaf(w, f0.y, acc[1]);
    acc[2] = fmaf(w, f1.x, acc[2]); acc[3] = fmaf(w, f1.y, acc[3]);
    acc[4] = fmaf(w, f2.x, acc[4]); acc[5] = fmaf(w, f2.y, acc[5]);
    acc[6] = fmaf(w, f3.x, acc[6]); acc[7] = fmaf(w, f3.y, acc[7]);
}

// agg core: team of 64 lanes computes relu(agg + bias) for node n -> float4
__device__ __forceinline__ float4 agg_node(const float* __restrict__ xw,
                                           const float* __restrict__ bias,
                                           int n, int lane) {
    const float4* __restrict__ xw4 = reinterpret_cast<const float4*>(xw);
    float4 bv = reinterpret_cast<const float4*>(bias)[lane];
    int s = g_eoff[n], e = g_eoff[n+1];
    float4 a0 = make_float4(0.f,0.f,0.f,0.f);
    float4 a1 = make_float4(0.f,0.f,0.f,0.f);
    int j = s;
    for (; j + 1 < e; j += 2) {
        int   sc0 = __ldg(&g_csr_src[j]);
        int   sc1 = __ldg(&g_csr_src[j+1]);
        float nr0 = __ldg(&g_csr_nrm[j]);
        float nr1 = __ldg(&g_csr_nrm[j+1]);
        float4 v0 = xw4[(size_t)sc0*64 + lane];
        float4 v1 = xw4[(size_t)sc1*64 + lane];
        a0.x = fmaf(nr0, v0.x, a0.x); a0.y = fmaf(nr0, v0.y, a0.y);
        a0.z = fmaf(nr0, v0.z, a0.z); a0.w = fmaf(nr0, v0.w, a0.w);
        a1.x = fmaf(nr1, v1.x, a1.x); a1.y = fmaf(nr1, v1.y, a1.y);
        a1.z = fmaf(nr1, v1.z, a1.z); a1.w = fmaf(nr1, v1.w, a1.w);
    }
    if (j < e) {
        int   sc0 = __ldg(&g_csr_src[j]);
        float nr0 = __ldg(&g_csr_nrm[j]);
        float4 v0 = xw4[(size_t)sc0*64 + lane];
        a0.x = fmaf(nr0, v0.x, a0.x); a0.y = fmaf(nr0, v0.y, a0.y);
        a0.z = fmaf(nr0, v0.z, a0.z); a0.w = fmaf(nr0, v0.w, a0.w);
    }
    float4 r;
    r.x = fmaxf(a0.x + a1.x + bv.x, 0.f); r.y = fmaxf(a0.y + a1.y + bv.y, 0.f);
    r.z = fmaxf(a0.z + a1.z + bv.z, 0.f); r.w = fmaxf(a0.w + a1.w + bv.w, 0.f);
    return r;
}

// ---------------- 4 (fused): spmm | agg_relu(layer-1) ----------------------------
__global__ void k_spmm_agg(const float* __restrict__ bias0) {
    __shared__ int2  sh[256];
    __shared__ float red[4][512];
    int blk = blockIdx.x, tid = threadIdx.x;
    int team = tid >> 6, lane = tid & 63;

    if (blk < SP_BLK) {
        // ---- spmm for superpixel blk ----
        int s = blk;
        int beg = g_poff4[4*s], end = g_poff4[4*s+4];
        const uint4* __restrict__ B4 = reinterpret_cast<const uint4*>(g_Bmh);
        const int2* __restrict__ ent = reinterpret_cast<const int2*>(g_ent4);
        float acc[8];
        #pragma unroll
        for (int i = 0; i < 8; i++) acc[i] = 0.f;
        for (int c0 = beg; c0 < end; c0 += 256) {
            int m = min(256, end - c0);
            __syncthreads();
            if (tid < m) sh[tid] = ent[c0 + tid];
            __syncthreads();
            for (int j = team; j < m; j += 4) {
                int2 e = sh[j];
                float2 wv = __half22float2(*reinterpret_cast<__half2*>(&e.y));
                size_t r = (size_t)e.x*64 + lane;
                uint4 vlo = B4[r];
                uint4 vhi = B4[r + 64];
                acc8(acc, wv.x, vlo);
                acc8(acc, wv.y, vhi);
            }
        }
        #pragma unroll
        for (int i = 0; i < 8; i++) red[team][lane*8+i] = acc[i];
        __syncthreads();
        #pragma unroll
        for (int c = tid; c < 512; c += 256)
            g_pool[(size_t)s*NPOOL + c] = red[0][c] + red[1][c] + red[2][c] + red[3][c];
    } else {
        // ---- agg layer-1 for 4 nodes ----
        int n = (blk - SP_BLK)*4 + team;
        float4 r = agg_node(g_xw, bias0, n, lane);
        reinterpret_cast<float4*>(g_Za)[(size_t)n*64 + lane] = r;
    }
}

// ---------------- agg_relu standalone (layer-2) ---------------------------------
__global__ void k_agg_relu(const float* __restrict__ xw, const float* __restrict__ bias,
                           float* __restrict__ out) {
    int tid = threadIdx.x;
    int team = tid >> 6, lane = tid & 63;
    int n = blockIdx.x*4 + team;
    float4 r = agg_node(xw, bias, n, lane);
    reinterpret_cast<float4*>(out)[(size_t)n*64 + lane] = r;
}

// ---------------- agg_relu + normalize + project (layer-3 tail) -----------------
__global__ void k_agg_out(const float* __restrict__ xw, const float* __restrict__ bias,
                          float* __restrict__ outp) {
    __shared__ float sh[4][CC];
    __shared__ float red[4][2];
    int tid = threadIdx.x;
    int team = tid >> 6, lane = tid & 63;
    int wlane = lane & 31, wi = lane >> 5;   // warp-in-team
    int n = blockIdx.x*4 + team;

    float4 r = agg_node(xw, bias, n, lane);

    float sq = r.x*r.x + r.y*r.y + r.z*r.z + r.w*r.w;
    #pragma unroll
    for (int o = 16; o > 0; o >>= 1) sq += __shfl_xor_sync(0xffffffffu, sq, o);
    if (wlane == 0) red[team][wi] = sq;
    __syncthreads();
    float nrm = fmaxf(sqrtf(red[team][0] + red[team][1]), 1e-12f);
    float inv = 1.0f / nrm;
    float4 v;
    v.x = r.x*inv; v.y = r.y*inv; v.z = r.z*inv; v.w = r.w*inv;

    reinterpret_cast<float4*>(outp + (size_t)NN*15)[(size_t)n*64 + lane] = v;  // cs_r
    sh[team][lane*4+0] = v.x; sh[team][lane*4+1] = v.y;
    sh[team][lane*4+2] = v.z; sh[team][lane*4+3] = v.w;
    __syncthreads();

    for (int k = wi; k < 15; k += 2) {
        float d = 0.f;
        #pragma unroll
        for (int i = wlane; i < CC; i += 32) d = fmaf(sh[team][i], g_wn[k*CC + i], d);
        #pragma unroll
        for (int o = 16; o > 0; o >>= 1) d += __shfl_xor_sync(0xffffffffu, d, o);
        if (wlane == 0) outp[(size_t)n*15 + k] = d;   // cs
    }
}

// ---------------- SGEMM with fused mix A-operand ----------------
__global__ void k_sgemm_mix(const float* __restrict__ Za, const float* __restrict__ B,
                            float* __restrict__ C, int offF) {
    __shared__ float As[8][128];
    __shared__ float Bs[8][64];
    int tid = threadIdx.x;
    int tx = tid & 15, ty = tid >> 4;
    int m0 = blockIdx.y*128, n0 = blockIdx.x*64;
    float acc[8][4];
    #pragma unroll
    for (int i=0;i<8;i++)
        #pragma unroll
        for (int j=0;j<4;j++) acc[i][j]=0.f;

    int a_m = tid >> 1;
    int a_k = (tid & 1) * 4;
    int b_k = tid >> 5;
    int b_n = (tid & 31) * 2;
    int m = m0 + a_m;
    bool mok = (m < NN);
    float inv = mok ? 0.5f / fmaxf(g_cnt[m], 1.0f) : 0.f;
    const float* poolRow = g_pool + (size_t)(mok ? m : 0)*NPOOL + offF;
    const float* zaRow   = Za     + (size_t)(mok ? m : 0)*CC;

    for (int kt = 0; kt < CC; kt += 8) {
        float4 av = make_float4(0.f,0.f,0.f,0.f);
        if (mok) {
            float4 hp = *reinterpret_cast<const float4*>(poolRow + kt + a_k);
            float4 za = *reinterpret_cast<const float4*>(zaRow   + kt + a_k);
            av.x = hp.x*inv + 0.5f*za.x; av.y = hp.y*inv + 0.5f*za.y;
            av.z = hp.z*inv + 0.5f*za.z; av.w = hp.w*inv + 0.5f*za.w;
        }
        As[a_k+0][a_m]=av.x; As[a_k+1][a_m]=av.y;
        As[a_k+2][a_m]=av.z; As[a_k+3][a_m]=av.w;
        float2 bv = *reinterpret_cast<const float2*>(B + (size_t)(kt+b_k)*CC + n0 + b_n);
        Bs[b_k][b_n]=bv.x; Bs[b_k][b_n+1]=bv.y;
        __syncthreads();
        #pragma unroll
        for (int k = 0; k < 8; k++) {
            float ar[8], br[4];
            #pragma unroll
            for (int i=0;i<8;i++) ar[i]=As[k][ty*8+i];
            #pragma unroll
            for (int j=0;j<4;j++) br[j]=Bs[k][tx*4+j];
            #pragma unroll
            for (int i=0;i<8;i++)
                #pragma unroll
                for (int j=0;j<4;j++) acc[i][j] = fmaf(ar[i], br[j], acc[i][j]);
        }
        __syncthreads();
    }
    #pragma unroll
    for (int i = 0; i < 8; i++) {
        int mm = m0 + ty*8 + i;
        if (mm < NN) {
            #pragma unroll
            for (int j = 0; j < 4; j++)
                C[(size_t)mm*CC + n0 + tx*4 + j] = acc[i][j];
        }
    }
}

// ---------------- launch ----------------
extern "C" void kernel_launch(void* const* d_in, const int* in_sizes, int n_in,
                              void* d_out, int out_size) {
    const float* image  = (const float*)d_in[0];
    const int*   labels = (const int*)  d_in[1];
    const int*   edges  = (const int*)  d_in[2];
    const float* probas = (const float*)d_in[3];
    const float* feats0 = (const float*)d_in[4];
    const float* feats1 = (const float*)d_in[5];
    const float* W0     = (const float*)d_in[6];
    const float* b0     = (const float*)d_in[7];
    const float* W1     = (const float*)d_in[8];
    const float* b1     = (const float*)d_in[9];
    const float* W2     = (const float*)d_in[10];
    const float* b2     = (const float*)d_in[11];
    const float* lin_w  = (const float*)d_in[12];
    float* outp = (float*)d_out;

    float *pZa, *pXw;
    cudaGetSymbolAddress((void**)&pZa, g_Za);
    cudaGetSymbolAddress((void**)&pXw, g_xw);

    // 1-4: init, fused builds
    k_init<<<(NN+255)/256, 256>>>();
    k_fuse1<<<B1_BLK + ED_BLK + TR_BLK, 256>>>(labels, image, edges, probas, feats0, feats1);
    k_scan2<<<3, 1024>>>(lin_w);
    k_fuse2<<<B2_BLK + SC_BLK + NN, 256>>>(labels, edges, W0);
    // 5: spmm fused with layer-1 aggregation (independent work)
    k_spmm_agg<<<SP_BLK + AG_BLK, 256>>>(b0);
    // 6-7: layer 2 (feats0)
    k_sgemm_mix<<<dim3(CC/64, (NN+127)/128), 256>>>(pZa, W1, pXw, 0);
    k_agg_relu<<<NN/4, 256>>>(pXw, b1, pZa);
    // 8-9: layer 3 (feats1) with fused output epilogue
    k_sgemm_mix<<<dim3(CC/64, (NN+127)/128), 256>>>(pZa, W2, pXw, CC);
    k_agg_out<<<NN/4, 256>>>(pXw, b2, outp);
    (void)in_sizes; (void)n_in; (void)out_size;
}

// round 17
// speedup vs baseline: 1.7983x; 1.0236x over previous
#include <cuda_runtime.h>
#include <cuda_fp16.h>
#include <math.h>
#include <stdint.h>

// ---------------- problem constants ----------------
#define BB   4
#define NSP  1500
#define NN   6000          // BB*NSP
#define N4   (NN*4)        // sharded counters (4 shards per superpixel)
#define EE   120000
#define HH   384
#define HWPX (HH*HH)       // 147456
#define NPX  (BB*HWPX)     // 589824
#define HS   96
#define HWI  (HS*HS)       // 9216
#define CC   256
#define NPOOL 512          // feats0 | feats1 columns
#define NENT (2*NPX)       // 1179648 pair-compressed pooling entries
#define CSR_E (EE+NN)      // folded self loops: one entry each, weight 2*dis^2
#define SIGMA_INV 5.0f     // 1/0.2

// fused-kernel block ranges
#define B1_BLK (HWPX/256)          // 576  build1
#define ED_BLK ((EE+255)/256)      // 469  edge_w_deg
#define TR_BLK (288*8*8)           // 18432 transpose
#define B2_BLK (HWPX/256)          // 576  build2
#define SC_BLK ((EE+NN+255)/256)   // 493  edge_scatter
#define X0_BLK (NN/4)              // 1500 x0 (4 nodes per block)
#define SP_BLK NN                  // 6000 spmm
#define AG_BLK (NN/4)              // 1500 agg layer-1

// ---------------- scratch (device globals; k_init re-inits every call) ----------
__device__ __half g_Bmh[(size_t)BB*HWI*NPOOL + NPOOL]; // 37.7 MB + 1 pad row
__device__ int4  g_ent4[NENT/2];                 // (q,w2,q,w2) pairs, 9.4 MB
__device__ float g_pool[(size_t)NN*NPOOL];
__device__ float g_Za[NN*CC];
__device__ float g_xw[NN*CC];
__device__ float g_cnt[NN];
__device__ float g_sumI4[N4*3];  // sharded image sums
__device__ float g_deg[NN];      // self-loop +2 folded into dis computation
__device__ float g_dis[NN];
__device__ float g_wnn[EE];
__device__ int   g_picnt[N4];    // sharded pooling counts
__device__ int   g_pfill4[N4];   // sharded fill cursors
__device__ int   g_poff4[N4+1];  // sharded offsets; s's range = [4s, 4s+4)
__device__ int   g_ecnt[NN];     // +1 self slot folded into scanE
__device__ int   g_eoff[NN+1];
__device__ int   g_efill[NN];
__device__ int2  g_csr2[CSR_E];  // packed (src, nrm-bits)
__device__ float g_wn[15*CC];

// ---------------- 0: init (self-healing regardless of prior stream state) -------
__global__ void k_init() {
    int i = blockIdx.x*blockDim.x + threadIdx.x;
    if (i >= NN) return;
    g_ecnt[i] = 0; g_efill[i] = 0;
    g_deg[i] = 0.f;
    #pragma unroll
    for (int k = 0; k < 4; k++) {
        g_picnt[i*4+k] = 0; g_pfill4[i*4+k] = 0;
        g_sumI4[(i*4+k)*3+0] = 0.f;
        g_sumI4[(i*4+k)*3+1] = 0.f;
        g_sumI4[(i*4+k)*3+2] = 0.f;
    }
}

// ---------------- 1 (fused): build1 | edge_w_deg | transpose ---------------------
__global__ void k_fuse1(const int* __restrict__ labels, const float* __restrict__ image,
                        const int* __restrict__ edges, const float* __restrict__ probas,
                        const float* __restrict__ f0, const float* __restrict__ f1) {
    __shared__ float t[32][33];
    int blk = blockIdx.x, tid = threadIdx.x;

    if (blk < B1_BLK) {
        int yx = blk*256 + tid;
        int shard = yx & 3;
        #pragma unroll
        for (int b = 0; b < BB; b++) {
            int s = b*NSP + labels[b*HWPX + yx];
            int cidx = s*4 + shard;
            atomicAdd(&g_picnt[cidx], 1);
            #pragma unroll
            for (int c = 0; c < 3; c++)
                atomicAdd(&g_sumI4[cidx*3+c], image[(size_t)(b*3+c)*HWPX + yx]);
        }
        return;
    }
    if (blk < B1_BLK + ED_BLK) {
        int e = (blk - B1_BLK)*256 + tid;
        if (e >= EE) return;
        int src = edges[e], dst = edges[EE + e];
        float w = expf(-fabsf(probas[src] - probas[dst]) * SIGMA_INV);
        g_wnn[e] = w;
        atomicAdd(&g_deg[dst], w);
        atomicAdd(&g_ecnt[dst], 1);
        return;
    }
    {
        int z3 = blk - (B1_BLK + ED_BLK);     // 0..18431
        int qb = z3 % 288; z3 /= 288;
        int cb = z3 % 8;   int z = z3 / 8;    // z: 0..7
        int b = z & 3;
        int colOff = (z >> 2) * CC;
        const float* __restrict__ src = (z < 4) ? f0 : f1;
        int q0 = qb*32, c0 = cb*32;
        int tx = tid & 31, ty = tid >> 5;     // 32 x 8
        #pragma unroll
        for (int i = 0; i < 32; i += 8) {
            int c = c0 + ty + i, q = q0 + tx;
            t[ty+i][tx] = src[((size_t)b*CC + c)*HWI + q];
        }
        __syncthreads();
        int qrow = tid >> 3, cg = tid & 7;
        __half2 h0 = __floats2half2_rn(t[cg*4+0][qrow], t[cg*4+1][qrow]);
        __half2 h1 = __floats2half2_rn(t[cg*4+2][qrow], t[cg*4+3][qrow]);
        uint2 o;
        o.x = *reinterpret_cast<unsigned*>(&h0);
        o.y = *reinterpret_cast<unsigned*>(&h1);
        size_t base = ((size_t)b*HWI + q0 + qrow)*NPOOL + colOff + c0 + cg*4;
        *reinterpret_cast<uint2*>(&g_Bmh[base]) = o;
    }
}

// ---------------- 2 (fused): scanP | scanE | norm_lin ---------------------------
__global__ void k_scan2(const float* __restrict__ lin_w) {
    __shared__ int wsum[32];
    __shared__ float red[8];
    int t = threadIdx.x, lane = t & 31, w = t >> 5;

    if (blockIdx.x == 0) {
        // ---- scanP: vectorized (1000 active threads x 6 int4 = 24000 counts) ----
        int pc[24]; int s = 0;
        int loc[24];
        if (t < 1000) {
            const int4* p4 = reinterpret_cast<const int4*>(g_picnt) + t*6;
            #pragma unroll
            for (int i = 0; i < 6; i++) {
                int4 v = p4[i];
                pc[i*4+0] = v.x; pc[i*4+1] = v.y; pc[i*4+2] = v.z; pc[i*4+3] = v.w;
            }
            #pragma unroll
            for (int i = 0; i < 24; i++) { loc[i] = s; s += 2*pc[i]; }
            #pragma unroll
            for (int g = 0; g < 6; g++) {
                int sp = t*6 + g;
                g_cnt[sp] = (float)(pc[g*4] + pc[g*4+1] + pc[g*4+2] + pc[g*4+3]);
            }
        }
        int x = s;
        #pragma unroll
        for (int o = 1; o < 32; o <<= 1) {
            int y = __shfl_up_sync(0xffffffffu, x, o);
            if (lane >= o) x += y;
        }
        if (lane == 31) wsum[w] = x;
        __syncthreads();
        if (w == 0) {
            int y = wsum[lane];
            #pragma unroll
            for (int o = 1; o < 32; o <<= 1) {
                int z2 = __shfl_up_sync(0xffffffffu, y, o);
                if (lane >= o) y += z2;
            }
            wsum[lane] = y;
        }
        __syncthreads();
        int base = (w > 0 ? wsum[w-1] : 0) + x - s;
        if (t < 1000) {
            int4* o4 = reinterpret_cast<int4*>(g_poff4) + t*6;
            #pragma unroll
            for (int i = 0; i < 6; i++) {
                int4 v;
                v.x = base + loc[i*4+0]; v.y = base + loc[i*4+1];
                v.z = base + loc[i*4+2]; v.w = base + loc[i*4+3];
                o4[i] = v;
            }
        }
        if (t == 1023) g_poff4[N4] = base;   // s==0 for t>=1000; base==total
    } else if (blockIdx.x == 1) {
        // ---- scanE: edge counts (+1 self slot) + dis ----
        int loc[6]; int s = 0;
        #pragma unroll
        for (int i = 0; i < 6; i++) {
            int idx = t*6 + i;
            int v = (idx < NN) ? (g_ecnt[idx] + 1) : 0;
            loc[i] = s; s += v;
            if (idx < NN) {
                float d = g_deg[idx] + 2.0f;
                g_dis[idx] = rsqrtf(fmaxf(d, 1e-30f));
            }
        }
        int x = s;
        #pragma unroll
        for (int o = 1; o < 32; o <<= 1) {
            int y = __shfl_up_sync(0xffffffffu, x, o);
            if (lane >= o) x += y;
        }
        if (lane == 31) wsum[w] = x;
        __syncthreads();
        if (w == 0) {
            int y = wsum[lane];
            #pragma unroll
            for (int o = 1; o < 32; o <<= 1) {
                int z2 = __shfl_up_sync(0xffffffffu, y, o);
                if (lane >= o) y += z2;
            }
            wsum[lane] = y;
        }
        __syncthreads();
        int base = (w > 0 ? wsum[w-1] : 0) + x - s;
        #pragma unroll
        for (int i = 0; i < 6; i++) {
            int idx = t*6 + i;
            if (idx < NN) g_eoff[idx] = base + loc[i];
        }
        if (t == 1023) g_eoff[NN] = base + s;
    } else {
        // ---- norm_lin (duplicated across 4 thread groups; identical values) ----
        int c = t & 255;
        int l2 = c & 31, w2 = c >> 5;
        for (int k = 0; k < 15; k++) {
            float v = lin_w[k*CC + c];
            float sq = v*v;
            #pragma unroll
            for (int o = 16; o > 0; o >>= 1) sq += __shfl_xor_sync(0xffffffffu, sq, o);
            if (l2 == 0) red[w2] = sq;
            __syncthreads();
            float tot = 0.f;
            #pragma unroll
            for (int i = 0; i < 8; i++) tot += red[i];
            g_wn[k*CC + c] = v / sqrtf(tot);
            __syncthreads();
        }
    }
}

// ---------------- 3 (fused): build2 | edge_scatter | x0 -------------------------
__global__ void k_fuse2(const int* __restrict__ labels, const int* __restrict__ edges,
                        const float* __restrict__ W0) {
    __shared__ float z0[4][3];
    int blk = blockIdx.x, tid = threadIdx.x;

    if (blk < B2_BLK) {
        int yx = blk*256 + tid;
        int shard = yx & 3;
        int y = yx / HH, x = yx % HH;
        const float scale = 95.0f/383.0f;
        float fy = y*scale, fx = x*scale;
        int y0 = (int)floorf(fy); if (y0 > 95) y0 = 95;
        int x0 = (int)floorf(fx); if (x0 > 95) x0 = 95;
        float wy = fy - y0, wx = fx - x0;
        int y1 = min(y0+1, 95);
        float w00 = (1.f-wy)*(1.f-wx), w01 = (1.f-wy)*wx;
        float w10 = wy*(1.f-wx),       w11 = wy*wx;
        if (x0 == 95) { w00 += w01; w01 = 0.f; w10 += w11; w11 = 0.f; }
        __half2 wt = __floats2half2_rn(w00, w01);
        __half2 wb = __floats2half2_rn(w10, w11);
        int wti = *reinterpret_cast<int*>(&wt);
        int wbi = *reinterpret_cast<int*>(&wb);
        int qt = y0*HS + x0, qb = y1*HS + x0;
        #pragma unroll
        for (int b = 0; b < BB; b++) {
            int s = b*NSP + labels[b*HWPX + yx];
            int cidx = s*4 + shard;
            int pos = g_poff4[cidx] + atomicAdd(&g_pfill4[cidx], 2);
            int4 e;
            e.x = b*HWI + qt;  e.y = wti;
            e.z = b*HWI + qb;  e.w = wbi;
            g_ent4[pos>>1] = e;
        }
        return;
    }
    if (blk < B2_BLK + SC_BLK) {
        int i = (blk - B2_BLK)*256 + tid;
        if (i >= EE + NN) return;
        if (i < EE) {
            int src = edges[i], dst = edges[EE + i];
            float w = g_wnn[i];
            int j = g_eoff[dst] + atomicAdd(&g_efill[dst], 1);
            g_csr2[j] = make_int2(src, __float_as_int(g_dis[src] * w * g_dis[dst]));
        } else {
            int n = i - EE;
            int j = g_eoff[n+1] - 1;
            g_csr2[j] = make_int2(n, __float_as_int(2.0f * g_dis[n] * g_dis[n]));
        }
        return;
    }
    {
        // ---- x0: 4 nodes per block, 64-lane teams, float4 stores ----
        int team = tid >> 6, lane = tid & 63;
        int n = (blk - (B2_BLK + SC_BLK))*4 + team;
        if (lane < 3) {
            float v = g_sumI4[(n*4+0)*3+lane] + g_sumI4[(n*4+1)*3+lane]
                    + g_sumI4[(n*4+2)*3+lane] + g_sumI4[(n*4+3)*3+lane];
            z0[team][lane] = v / fmaxf(g_cnt[n], 1.0f);
        }
        __syncthreads();
        float a = z0[team][0], b = z0[team][1], c = z0[team][2];
        float4 w0 = reinterpret_cast<const float4*>(W0)[lane];
        float4 w1 = reinterpret_cast<const float4*>(W0 + CC)[lane];
        float4 w2 = reinterpret_cast<const float4*>(W0 + 2*CC)[lane];
        float4 r;
        r.x = a*w0.x + b*w1.x + c*w2.x;
        r.y = a*w0.y + b*w1.y + c*w2.y;
        r.z = a*w0.z + b*w1.z + c*w2.z;
        r.w = a*w0.w + b*w1.w + c*w2.w;
        reinterpret_cast<float4*>(g_xw)[(size_t)n*64 + lane] = r;
    }
}

// ---------------- shared device helpers ----------------
__device__ __forceinline__ void acc8(float* acc, float w, uint4 v) {
    float2 f0 = __half22float2(*(const __half2*)&v.x);
    float2 f1 = __half22float2(*(const __half2*)&v.y);
    float2 f2 = __half22float2(*(const __half2*)&v.z);
    float2 f3 = __half22float2(*(const __half2*)&v.w);
    acc[0] = fmaf(w, f0.x, acc[0]); acc[1] = fmaf(w, f0.y, acc[1]);
    acc[2] = fmaf(w, f1.x, acc[2]); acc[3] = fmaf(w, f1.y, acc[3]);
    acc[4] = fmaf(w, f2.x, acc[4]); acc[5] = fmaf(w, f2.y, acc[5]);
    acc[6] = fmaf(w, f3.x, acc[6]); acc[7] = fmaf(w, f3.y, acc[7]);
}

// agg core: team of 64 lanes computes relu(agg + bias) for node n -> float4
__device__ __forceinline__ float4 agg_node(const float* __restrict__ xw,
                                           const float* __restrict__ bias,
                                           int n, int lane) {
    const float4* __restrict__ xw4 = reinterpret_cast<const float4*>(xw);
    float4 bv = reinterpret_cast<const float4*>(bias)[lane];
    int s = g_eoff[n], e = g_eoff[n+1];
    float4 a0 = make_float4(0.f,0.f,0.f,0.f);
    float4 a1 = make_float4(0.f,0.f,0.f,0.f);
    int j = s;
    for (; j + 1 < e; j += 2) {
        int2 p0 = __ldg(&g_csr2[j]);
        int2 p1 = __ldg(&g_csr2[j+1]);
        float nr0 = __int_as_float(p0.y);
        float nr1 = __int_as_float(p1.y);
        float4 v0 = xw4[(size_t)p0.x*64 + lane];
        float4 v1 = xw4[(size_t)p1.x*64 + lane];
        a0.x = fmaf(nr0, v0.x, a0.x); a0.y = fmaf(nr0, v0.y, a0.y);
        a0.z = fmaf(nr0, v0.z, a0.z); a0.w = fmaf(nr0, v0.w, a0.w);
        a1.x = fmaf(nr1, v1.x, a1.x); a1.y = fmaf(nr1, v1.y, a1.y);
        a1.z = fmaf(nr1, v1.z, a1.z); a1.w = fmaf(nr1, v1.w, a1.w);
    }
    if (j < e) {
        int2 p0 = __ldg(&g_csr2[j]);
        float nr0 = __int_as_float(p0.y);
        float4 v0 = xw4[(size_t)p0.x*64 + lane];
        a0.x = fmaf(nr0, v0.x, a0.x); a0.y = fmaf(nr0, v0.y, a0.y);
        a0.z = fmaf(nr0, v0.z, a0.z); a0.w = fmaf(nr0, v0.w, a0.w);
    }
    float4 r;
    r.x = fmaxf(a0.x + a1.x + bv.x, 0.f); r.y = fmaxf(a0.y + a1.y + bv.y, 0.f);
    r.z = fmaxf(a0.z + a1.z + bv.z, 0.f); r.w = fmaxf(a0.w + a1.w + bv.w, 0.f);
    return r;
}

// ---------------- 4 (fused): spmm | agg_relu(layer-1) ----------------------------
__global__ void k_spmm_agg(const float* __restrict__ bias0) {
    __shared__ int2  sh[256];
    __shared__ float red[4][512];
    int blk = blockIdx.x, tid = threadIdx.x;
    int team = tid >> 6, lane = tid & 63;

    if (blk < SP_BLK) {
        int s = blk;
        int beg = g_poff4[4*s], end = g_poff4[4*s+4];
        const uint4* __restrict__ B4 = reinterpret_cast<const uint4*>(g_Bmh);
        const int2* __restrict__ ent = reinterpret_cast<const int2*>(g_ent4);
        float acc[8];
        #pragma unroll
        for (int i = 0; i < 8; i++) acc[i] = 0.f;
        for (int c0 = beg; c0 < end; c0 += 256) {
            int m = min(256, end - c0);
            __syncthreads();
            if (tid < m) sh[tid] = ent[c0 + tid];
            __syncthreads();
            for (int j = team; j < m; j += 4) {
                int2 e = sh[j];
                float2 wv = __half22float2(*reinterpret_cast<__half2*>(&e.y));
                size_t r = (size_t)e.x*64 + lane;
                uint4 vlo = B4[r];
                uint4 vhi = B4[r + 64];
                acc8(acc, wv.x, vlo);
                acc8(acc, wv.y, vhi);
            }
        }
        #pragma unroll
        for (int i = 0; i < 8; i++) red[team][lane*8+i] = acc[i];
        __syncthreads();
        #pragma unroll
        for (int c = tid; c < 512; c += 256)
            g_pool[(size_t)s*NPOOL + c] = red[0][c] + red[1][c] + red[2][c] + red[3][c];
    } else {
        int n = (blk - SP_BLK)*4 + team;
        float4 r = agg_node(g_xw, bias0, n, lane);
        reinterpret_cast<float4*>(g_Za)[(size_t)n*64 + lane] = r;
    }
}

// ---------------- agg_relu standalone (layer-2) ---------------------------------
__global__ void k_agg_relu(const float* __restrict__ xw, const float* __restrict__ bias,
                           float* __restrict__ out) {
    int tid = threadIdx.x;
    int team = tid >> 6, lane = tid & 63;
    int n = blockIdx.x*4 + team;
    float4 r = agg_node(xw, bias, n, lane);
    reinterpret_cast<float4*>(out)[(size_t)n*64 + lane] = r;
}

// ---------------- agg_relu + normalize + project (layer-3 tail) -----------------
__global__ void k_agg_out(const float* __restrict__ xw, const float* __restrict__ bias,
                          float* __restrict__ outp) {
    __shared__ float sh[4][CC];
    __shared__ float red[4][2];
    int tid = threadIdx.x;
    int team = tid >> 6, lane = tid & 63;
    int wlane = lane & 31, wi = lane >> 5;   // warp-in-team
    int n = blockIdx.x*4 + team;

    float4 r = agg_node(xw, bias, n, lane);

    float sq = r.x*r.x + r.y*r.y + r.z*r.z + r.w*r.w;
    #pragma unroll
    for (int o = 16; o > 0; o >>= 1) sq += __shfl_xor_sync(0xffffffffu, sq, o);
    if (wlane == 0) red[team][wi] = sq;
    __syncthreads();
    float nrm = fmaxf(sqrtf(red[team][0] + red[team][1]), 1e-12f);
    float inv = 1.0f / nrm;
    float4 v;
    v.x = r.x*inv; v.y = r.y*inv; v.z = r.z*inv; v.w = r.w*inv;

    reinterpret_cast<float4*>(outp + (size_t)NN*15)[(size_t)n*64 + lane] = v;  // cs_r
    sh[team][lane*4+0] = v.x; sh[team][lane*4+1] = v.y;
    sh[team][lane*4+2] = v.z; sh[team][lane*4+3] = v.w;
    __syncthreads();

    for (int k = wi; k < 15; k += 2) {
        float d = 0.f;
        #pragma unroll
        for (int i = wlane; i < CC; i += 32) d = fmaf(sh[team][i], g_wn[k*CC + i], d);
        #pragma unroll
        for (int o = 16; o > 0; o >>= 1) d += __shfl_xor_sync(0xffffffffu, d, o);
        if (wlane == 0) outp[(size_t)n*15 + k] = d;   // cs
    }
}

// ---------------- SGEMM with fused mix A-operand ----------------
__global__ void k_sgemm_mix(const float* __restrict__ Za, const float* __restrict__ B,
                            float* __restrict__ C, int offF) {
    __shared__ float As[8][128];
    __shared__ float Bs[8][64];
    int tid = threadIdx.x;
    int tx = tid & 15, ty = tid >> 4;
    int m0 = blockIdx.y*128, n0 = blockIdx.x*64;
    float acc[8][4];
    #pragma unroll
    for (int i=0;i<8;i++)
        #pragma unroll
        for (int j=0;j<4;j++) acc[i][j]=0.f;

    int a_m = tid >> 1;
    int a_k = (tid & 1) * 4;
    int b_k = tid >> 5;
    int b_n = (tid & 31) * 2;
    int m = m0 + a_m;
    bool mok = (m < NN);
    float inv = mok ? 0.5f / fmaxf(g_cnt[m], 1.0f) : 0.f;
    const float* poolRow = g_pool + (size_t)(mok ? m : 0)*NPOOL + offF;
    const float* zaRow   = Za     + (size_t)(mok ? m : 0)*CC;

    for (int kt = 0; kt < CC; kt += 8) {
        float4 av = make_float4(0.f,0.f,0.f,0.f);
        if (mok) {
            float4 hp = *reinterpret_cast<const float4*>(poolRow + kt + a_k);
            float4 za = *reinterpret_cast<const float4*>(zaRow   + kt + a_k);
            av.x = hp.x*inv + 0.5f*za.x; av.y = hp.y*inv + 0.5f*za.y;
            av.z = hp.z*inv + 0.5f*za.z; av.w = hp.w*inv + 0.5f*za.w;
        }
        As[a_k+0][a_m]=av.x; As[a_k+1][a_m]=av.y;
        As[a_k+2][a_m]=av.z; As[a_k+3][a_m]=av.w;
        float2 bv = *reinterpret_cast<const float2*>(B + (size_t)(kt+b_k)*CC + n0 + b_n);
        Bs[b_k][b_n]=bv.x; Bs[b_k][b_n+1]=bv.y;
        __syncthreads();
        #pragma unroll
        for (int k = 0; k < 8; k++) {
            float ar[8], br[4];
            #pragma unroll
            for (int i=0;i<8;i++) ar[i]=As[k][ty*8+i];
            #pragma unroll
            for (int j=0;j<4;j++) br[j]=Bs[k][tx*4+j];
            #pragma unroll
            for (int i=0;i<8;i++)
                #pragma unroll
                for (int j=0;j<4;j++) acc[i][j] = fmaf(ar[i], br[j], acc[i][j]);
        }
        __syncthreads();
    }
    #pragma unroll
    for (int i = 0; i < 8; i++) {
        int mm = m0 + ty*8 + i;
        if (mm < NN) {
            #pragma unroll
            for (int j = 0; j < 4; j++)
                C[(size_t)mm*CC + n0 + tx*4 + j] = acc[i][j];
        }
    }
}

// ---------------- launch ----------------
extern "C" void kernel_launch(void* const* d_in, const int* in_sizes, int n_in,
                              void* d_out, int out_size) {
    const float* image  = (const float*)d_in[0];
    const int*   labels = (const int*)  d_in[1];
    const int*   edges  = (const int*)  d_in[2];
    const float* probas = (const float*)d_in[3];
    const float* feats0 = (const float*)d_in[4];
    const float* feats1 = (const float*)d_in[5];
    const float* W0     = (const float*)d_in[6];
    const float* b0     = (const float*)d_in[7];
    const float* W1     = (const float*)d_in[8];
    const float* b1     = (const float*)d_in[9];
    const float* W2     = (const float*)d_in[10];
    const float* b2     = (const float*)d_in[11];
    const float* lin_w  = (const float*)d_in[12];
    float* outp = (float*)d_out;

    float *pZa, *pXw;
    cudaGetSymbolAddress((void**)&pZa, g_Za);
    cudaGetSymbolAddress((void**)&pXw, g_xw);

    // 1-4: init, fused builds
    k_init<<<(NN+255)/256, 256>>>();
    k_fuse1<<<B1_BLK + ED_BLK + TR_BLK, 256>>>(labels, image, edges, probas, feats0, feats1);
    k_scan2<<<3, 1024>>>(lin_w);
    k_fuse2<<<B2_BLK + SC_BLK + X0_BLK, 256>>>(labels, edges, W0);
    // 5: spmm fused with layer-1 aggregation (independent work)
    k_spmm_agg<<<SP_BLK + AG_BLK, 256>>>(b0);
    // 6-7: layer 2 (feats0)
    k_sgemm_mix<<<dim3(CC/64, (NN+127)/128), 256>>>(pZa, W1, pXw, 0);
    k_agg_relu<<<NN/4, 256>>>(pXw, b1, pZa);
    // 8-9: layer 3 (feats1) with fused output epilogue
    k_sgemm_mix<<<dim3(CC/64, (NN+127)/128), 256>>>(pZa, W2, pXw, CC);
    k_agg_out<<<NN/4, 256>>>(pXw, b2, outp);
    (void)in_sizes; (void)n_in; (void)out_size;
}